// round 1
// baseline (speedup 1.0000x reference)
#include <cuda_runtime.h>
#include <math.h>

#define NTHREADS 256
#define BM 64
#define BN 64
#define BK 16

#define B_ 4
#define T_ 2048
#define D_ 1024
#define M_ (B_*T_)

// ---------------- scratch (__device__ globals: allocation-guard safe) ----------
__device__ float g_h [M_*D_];
__device__ float g_q [M_*D_];
__device__ float g_k [M_*D_];
__device__ float g_v [M_*D_];
__device__ float g_s [(size_t)B_*T_*T_];
__device__ float g_y [M_*D_];
__device__ float g_h2[M_*D_];
__device__ float g_m1[M_*D_];

// ---------------- LayerNorm (reproduces reference's buggy LN) ------------------
// h = (x - mu/sqrt(var_unbiased)) * gamma + beta
__global__ void ln_kernel(const float* __restrict__ x, const float* __restrict__ gamma,
                          const float* __restrict__ beta, float* __restrict__ out)
{
    const int row = blockIdx.x;
    const float* xr = x + (size_t)row * D_;
    float s = 0.f, ss = 0.f;
    for (int i = threadIdx.x; i < D_; i += NTHREADS) {
        float v = xr[i];
        s += v; ss += v * v;
    }
    #pragma unroll
    for (int o = 16; o; o >>= 1) {
        s  += __shfl_xor_sync(0xffffffffu, s, o);
        ss += __shfl_xor_sync(0xffffffffu, ss, o);
    }
    __shared__ float sh_s[8], sh_ss[8];
    const int w = threadIdx.x >> 5;
    if ((threadIdx.x & 31) == 0) { sh_s[w] = s; sh_ss[w] = ss; }
    __syncthreads();
    s = 0.f; ss = 0.f;
    #pragma unroll
    for (int i = 0; i < 8; i++) { s += sh_s[i]; ss += sh_ss[i]; }
    const float mu  = s * (1.0f / D_);
    const float var = (ss - (float)D_ * mu * mu) * (1.0f / (float)(D_ - 1));
    const float c   = mu * rsqrtf(var);
    float* outr = out + (size_t)row * D_;
    for (int i = threadIdx.x; i < D_; i += NTHREADS)
        outr[i] = (xr[i] - c) * gamma[i] + beta[i];
}

// ---------------- generic NN GEMM: C[M,N] = A[M,K] @ B[K,N] (+ epilogue) -------
// EPI 0: plain; EPI 1: relu(acc + bias[col]); EPI 2: acc + bias[col] + resid
template<int EPI>
__global__ void gemm_nn_kernel(const float* __restrict__ A, const float* __restrict__ Bm,
                               float* __restrict__ C, int M, int N, int K,
                               const float* __restrict__ bias, const float* __restrict__ resid)
{
    __shared__ float As[BK][BM];
    __shared__ float Bs[BK][BN];
    const int bm = blockIdx.y * BM;
    const int bn = blockIdx.x * BN;
    const int tid = threadIdx.x;
    const int tx = tid & 15;
    const int ty = tid >> 4;
    const int a_row = tid & 63;
    const int a_k4  = (tid >> 6) << 2;
    const int b_kr  = tid >> 4;
    const int b_c4  = (tid & 15) << 2;

    float acc[4][4] = {};
    const float* Ap = A  + (size_t)(bm + a_row) * K + a_k4;
    const float* Bp = Bm + (size_t)b_kr * N + bn + b_c4;

    for (int k0 = 0; k0 < K; k0 += BK) {
        float4 av = *(const float4*)(Ap + k0);
        As[a_k4+0][a_row] = av.x;
        As[a_k4+1][a_row] = av.y;
        As[a_k4+2][a_row] = av.z;
        As[a_k4+3][a_row] = av.w;
        *(float4*)&Bs[b_kr][b_c4] = *(const float4*)(Bp + (size_t)k0 * N);
        __syncthreads();
        #pragma unroll
        for (int kk = 0; kk < BK; kk++) {
            float4 a = *(const float4*)&As[kk][ty << 2];
            float4 b = *(const float4*)&Bs[kk][tx << 2];
            acc[0][0] += a.x*b.x; acc[0][1] += a.x*b.y; acc[0][2] += a.x*b.z; acc[0][3] += a.x*b.w;
            acc[1][0] += a.y*b.x; acc[1][1] += a.y*b.y; acc[1][2] += a.y*b.z; acc[1][3] += a.y*b.w;
            acc[2][0] += a.z*b.x; acc[2][1] += a.z*b.y; acc[2][2] += a.z*b.z; acc[2][3] += a.z*b.w;
            acc[3][0] += a.w*b.x; acc[3][1] += a.w*b.y; acc[3][2] += a.w*b.z; acc[3][3] += a.w*b.w;
        }
        __syncthreads();
    }

    #pragma unroll
    for (int i = 0; i < 4; i++) {
        const int r = bm + (ty << 2) + i;
        const int cbase = bn + (tx << 2);
        float4 o;
        float* oc = (float*)&o;
        #pragma unroll
        for (int j = 0; j < 4; j++) {
            float val = acc[i][j];
            if (EPI == 1) val = fmaxf(val + bias[cbase + j], 0.0f);
            else if (EPI == 2) val = val + bias[cbase + j] + resid[(size_t)r * N + cbase + j];
            oc[j] = val;
        }
        *(float4*)&C[(size_t)r * N + cbase] = o;
    }
}

// ---------------- scores: S[b,q,t] = scale * Q[b,q,:].K[b,t,:], causal mask ----
__global__ void scores_kernel(const float* __restrict__ Q, const float* __restrict__ Kmat,
                              float* __restrict__ S)
{
    const int b  = blockIdx.z;
    const int bm = blockIdx.y * BM;   // q tile
    const int bn = blockIdx.x * BN;   // t tile
    const int tid = threadIdx.x;
    float* Sb = S + (size_t)b * T_ * T_;

    if (bn > bm + (BM - 1)) {         // fully above diagonal: masked, skip GEMM
        for (int idx = tid; idx < BM * BN; idx += NTHREADS) {
            const int r = idx >> 6, c = idx & 63;
            Sb[(size_t)(bm + r) * T_ + bn + c] = -1e30f;
        }
        return;
    }

    __shared__ float As[BK][BM];
    __shared__ float Bs[BK][BN];
    const int tx = tid & 15, ty = tid >> 4;
    const int l_row = tid & 63;
    const int l_k4  = (tid >> 6) << 2;
    const float* Qp = Q    + (size_t)b * T_ * D_ + (size_t)(bm + l_row) * D_ + l_k4;
    const float* Kp = Kmat + (size_t)b * T_ * D_ + (size_t)(bn + l_row) * D_ + l_k4;

    float acc[4][4] = {};
    for (int k0 = 0; k0 < D_; k0 += BK) {
        float4 av = *(const float4*)(Qp + k0);
        As[l_k4+0][l_row] = av.x; As[l_k4+1][l_row] = av.y;
        As[l_k4+2][l_row] = av.z; As[l_k4+3][l_row] = av.w;
        float4 bv = *(const float4*)(Kp + k0);
        Bs[l_k4+0][l_row] = bv.x; Bs[l_k4+1][l_row] = bv.y;
        Bs[l_k4+2][l_row] = bv.z; Bs[l_k4+3][l_row] = bv.w;
        __syncthreads();
        #pragma unroll
        for (int kk = 0; kk < BK; kk++) {
            float4 a = *(const float4*)&As[kk][ty << 2];
            float4 bq = *(const float4*)&Bs[kk][tx << 2];
            acc[0][0] += a.x*bq.x; acc[0][1] += a.x*bq.y; acc[0][2] += a.x*bq.z; acc[0][3] += a.x*bq.w;
            acc[1][0] += a.y*bq.x; acc[1][1] += a.y*bq.y; acc[1][2] += a.y*bq.z; acc[1][3] += a.y*bq.w;
            acc[2][0] += a.z*bq.x; acc[2][1] += a.z*bq.y; acc[2][2] += a.z*bq.z; acc[2][3] += a.z*bq.w;
            acc[3][0] += a.w*bq.x; acc[3][1] += a.w*bq.y; acc[3][2] += a.w*bq.z; acc[3][3] += a.w*bq.w;
        }
        __syncthreads();
    }

    const float scale = 0.03125f;   // 1/sqrt(1024)
    #pragma unroll
    for (int i = 0; i < 4; i++) {
        const int q = bm + (ty << 2) + i;
        #pragma unroll
        for (int j = 0; j < 4; j++) {
            const int t = bn + (tx << 2) + j;
            Sb[(size_t)q * T_ + t] = (t <= q) ? acc[i][j] * scale : -1e30f;
        }
    }
}

// ---------------- row softmax over T_ (in place) --------------------------------
__global__ void softmax_kernel(float* __restrict__ S)
{
    const int row = blockIdx.x;           // 0..M_-1
    const int b = row >> 11;
    const int q = row & (T_ - 1);
    float* r = S + (size_t)b * T_ * T_ + (size_t)q * T_;

    float m = -1e30f;
    for (int i = threadIdx.x; i < T_; i += NTHREADS) m = fmaxf(m, r[i]);
    #pragma unroll
    for (int o = 16; o; o >>= 1) m = fmaxf(m, __shfl_xor_sync(0xffffffffu, m, o));
    __shared__ float shm[8], shs[8];
    const int w = threadIdx.x >> 5;
    if ((threadIdx.x & 31) == 0) shm[w] = m;
    __syncthreads();
    m = shm[0];
    #pragma unroll
    for (int i = 1; i < 8; i++) m = fmaxf(m, shm[i]);

    float s = 0.f;
    for (int i = threadIdx.x; i < T_; i += NTHREADS) {
        float e = __expf(r[i] - m);
        r[i] = e;
        s += e;
    }
    #pragma unroll
    for (int o = 16; o; o >>= 1) s += __shfl_xor_sync(0xffffffffu, s, o);
    if ((threadIdx.x & 31) == 0) shs[w] = s;
    __syncthreads();
    s = 0.f;
    #pragma unroll
    for (int i = 0; i < 8; i++) s += shs[i];
    const float inv = 1.0f / s;
    for (int i = threadIdx.x; i < T_; i += NTHREADS) r[i] *= inv;
}

// ---------------- Y[b,q,d] = sum_t P[b,q,t] V[b,t,d] + x[b,q,d] ----------------
__global__ void av_kernel(const float* __restrict__ P, const float* __restrict__ V,
                          const float* __restrict__ x, float* __restrict__ Y)
{
    const int b  = blockIdx.z;
    const int bm = blockIdx.y * BM;   // q tile
    const int bn = blockIdx.x * BN;   // d tile
    __shared__ float As[BK][BM];
    __shared__ float Bs[BK][BN];
    const int tid = threadIdx.x;
    const int tx = tid & 15, ty = tid >> 4;
    const int a_row = tid & 63;
    const int a_k4  = (tid >> 6) << 2;
    const int b_kr  = tid >> 4;
    const int b_c4  = (tid & 15) << 2;

    const float* Pb = P + (size_t)b * T_ * T_;
    const float* Vb = V + (size_t)b * T_ * D_;
    const int kend = (bm + BM < T_) ? (bm + BM) : T_;   // causal: P zero beyond q

    float acc[4][4] = {};
    const float* Ap = Pb + (size_t)(bm + a_row) * T_ + a_k4;
    const float* Bp = Vb + (size_t)b_kr * D_ + bn + b_c4;

    for (int k0 = 0; k0 < kend; k0 += BK) {
        float4 av = *(const float4*)(Ap + k0);
        As[a_k4+0][a_row] = av.x;
        As[a_k4+1][a_row] = av.y;
        As[a_k4+2][a_row] = av.z;
        As[a_k4+3][a_row] = av.w;
        *(float4*)&Bs[b_kr][b_c4] = *(const float4*)(Bp + (size_t)k0 * D_);
        __syncthreads();
        #pragma unroll
        for (int kk = 0; kk < BK; kk++) {
            float4 a = *(const float4*)&As[kk][ty << 2];
            float4 bq = *(const float4*)&Bs[kk][tx << 2];
            acc[0][0] += a.x*bq.x; acc[0][1] += a.x*bq.y; acc[0][2] += a.x*bq.z; acc[0][3] += a.x*bq.w;
            acc[1][0] += a.y*bq.x; acc[1][1] += a.y*bq.y; acc[1][2] += a.y*bq.z; acc[1][3] += a.y*bq.w;
            acc[2][0] += a.z*bq.x; acc[2][1] += a.z*bq.y; acc[2][2] += a.z*bq.z; acc[2][3] += a.z*bq.w;
            acc[3][0] += a.w*bq.x; acc[3][1] += a.w*bq.y; acc[3][2] += a.w*bq.z; acc[3][3] += a.w*bq.w;
        }
        __syncthreads();
    }

    #pragma unroll
    for (int i = 0; i < 4; i++) {
        const int q = bm + (ty << 2) + i;
        const int cbase = bn + (tx << 2);
        const size_t gidx = ((size_t)(b * T_ + q)) * D_ + cbase;
        float4 xv = *(const float4*)&x[gidx];
        float4 o;
        o.x = acc[i][0] + xv.x;
        o.y = acc[i][1] + xv.y;
        o.z = acc[i][2] + xv.z;
        o.w = acc[i][3] + xv.w;
        *(float4*)&Y[gidx] = o;
    }
}

// ---------------- launch --------------------------------------------------------
extern "C" void kernel_launch(void* const* d_in, const int* in_sizes, int n_in,
                              void* d_out, int out_size)
{
    const float* x   = (const float*)d_in[0];
    const float* g1  = (const float*)d_in[1];
    const float* be1 = (const float*)d_in[2];
    const float* wq  = (const float*)d_in[3];
    const float* wk  = (const float*)d_in[4];
    const float* wv  = (const float*)d_in[5];
    const float* g2  = (const float*)d_in[6];
    const float* be2 = (const float*)d_in[7];
    const float* W1  = (const float*)d_in[8];
    const float* b1  = (const float*)d_in[9];
    const float* W2  = (const float*)d_in[10];
    const float* b2  = (const float*)d_in[11];
    float* out = (float*)d_out;

    float *p_h, *p_q, *p_k, *p_v, *p_s, *p_y, *p_h2, *p_m1;
    cudaGetSymbolAddress((void**)&p_h,  g_h);
    cudaGetSymbolAddress((void**)&p_q,  g_q);
    cudaGetSymbolAddress((void**)&p_k,  g_k);
    cudaGetSymbolAddress((void**)&p_v,  g_v);
    cudaGetSymbolAddress((void**)&p_s,  g_s);
    cudaGetSymbolAddress((void**)&p_y,  g_y);
    cudaGetSymbolAddress((void**)&p_h2, g_h2);
    cudaGetSymbolAddress((void**)&p_m1, g_m1);

    const dim3 gemm_grid(D_ / BN, M_ / BM);        // (16, 128)
    const dim3 sc_grid(T_ / BN, T_ / BM, B_);      // (32, 32, 4)
    const dim3 av_grid(D_ / BN, T_ / BM, B_);      // (16, 32, 4)

    ln_kernel<<<M_, NTHREADS>>>(x, g1, be1, p_h);
    gemm_nn_kernel<0><<<gemm_grid, NTHREADS>>>(p_h, wq, p_q, M_, D_, D_, nullptr, nullptr);
    gemm_nn_kernel<0><<<gemm_grid, NTHREADS>>>(p_h, wk, p_k, M_, D_, D_, nullptr, nullptr);
    gemm_nn_kernel<0><<<gemm_grid, NTHREADS>>>(p_h, wv, p_v, M_, D_, D_, nullptr, nullptr);
    scores_kernel<<<sc_grid, NTHREADS>>>(p_q, p_k, p_s);
    softmax_kernel<<<M_, NTHREADS>>>(p_s);
    av_kernel<<<av_grid, NTHREADS>>>(p_s, p_v, x, p_y);
    ln_kernel<<<M_, NTHREADS>>>(p_y, g2, be2, p_h2);
    gemm_nn_kernel<1><<<gemm_grid, NTHREADS>>>(p_h2, W1, p_m1, M_, D_, D_, b1, nullptr);
    gemm_nn_kernel<2><<<gemm_grid, NTHREADS>>>(p_m1, W2, out, M_, D_, D_, b2, p_y);
}

// round 2
// speedup vs baseline: 3.1900x; 3.1900x over previous
#include <cuda_runtime.h>
#include <math.h>
#include <stdint.h>

#define B_ 4
#define T_ 2048
#define D_ 1024
#define M_ (B_*T_)

#define NT 256        // threads per block for GEMM kernels
#define BM 128
#define BN 128
#define BK 32
#define PADA 36       // stride for [rows][BK] tiles (A-style), floats
#define PADB 132      // stride for [BK][cols] tiles (B-style), floats

// ---------------- scratch (__device__ globals: allocation-guard safe) ----------
__device__ float g_h [M_*D_];
__device__ float g_q [M_*D_];
__device__ float g_k [M_*D_];
__device__ float g_v [M_*D_];
__device__ float g_s [(size_t)B_*T_*T_];
__device__ float g_y [M_*D_];
__device__ float g_h2[M_*D_];
__device__ float g_m1[M_*D_];

// ---------------- helpers -------------------------------------------------------
__device__ __forceinline__ uint32_t tf32r(float x) {
    uint32_t y;
    asm("cvt.rna.tf32.f32 %0, %1;" : "=r"(y) : "f"(x));
    return y;
}

__device__ __forceinline__ void mma_tf32(float c[4], uint32_t a0, uint32_t a1,
                                         uint32_t a2, uint32_t a3,
                                         uint32_t b0, uint32_t b1)
{
    asm volatile(
        "mma.sync.aligned.m16n8k8.row.col.f32.tf32.tf32.f32 "
        "{%0,%1,%2,%3}, {%4,%5,%6,%7}, {%8,%9}, {%0,%1,%2,%3};"
        : "+f"(c[0]), "+f"(c[1]), "+f"(c[2]), "+f"(c[3])
        : "r"(a0), "r"(a1), "r"(a2), "r"(a3), "r"(b0), "r"(b1));
}

// ---------------- LayerNorm (reproduces reference's buggy LN) ------------------
__global__ void ln_kernel(const float* __restrict__ x, const float* __restrict__ gamma,
                          const float* __restrict__ beta, float* __restrict__ out)
{
    const int row = blockIdx.x;
    const float* xr = x + (size_t)row * D_;
    float s = 0.f, ss = 0.f;
    for (int i = threadIdx.x; i < D_; i += 256) {
        float v = xr[i];
        s += v; ss += v * v;
    }
    #pragma unroll
    for (int o = 16; o; o >>= 1) {
        s  += __shfl_xor_sync(0xffffffffu, s, o);
        ss += __shfl_xor_sync(0xffffffffu, ss, o);
    }
    __shared__ float sh_s[8], sh_ss[8];
    const int w = threadIdx.x >> 5;
    if ((threadIdx.x & 31) == 0) { sh_s[w] = s; sh_ss[w] = ss; }
    __syncthreads();
    s = 0.f; ss = 0.f;
    #pragma unroll
    for (int i = 0; i < 8; i++) { s += sh_s[i]; ss += sh_ss[i]; }
    const float mu  = s * (1.0f / D_);
    const float var = (ss - (float)D_ * mu * mu) * (1.0f / (float)(D_ - 1));
    const float c   = mu * rsqrtf(var);
    float* outr = out + (size_t)row * D_;
    for (int i = threadIdx.x; i < D_; i += 256)
        outr[i] = (xr[i] - c) * gamma[i] + beta[i];
}

// ---------------- tf32 tensor-core GEMM: C = A[M,K] @ B[K,N] (+epilogue) -------
// EPI 0: plain; 1: relu(acc+bias); 2: acc+bias+resid
template<int EPI>
__global__ __launch_bounds__(NT, 1)
void gemm_tf32(const float* __restrict__ A, const float* __restrict__ Bm,
               float* __restrict__ C, const float* __restrict__ bias,
               const float* __restrict__ resid, int M, int N, int K)
{
    __shared__ float As[BM][PADA];
    __shared__ float Bs[BK][PADB];

    const int tid  = threadIdx.x;
    const int lane = tid & 31;
    const int warp = tid >> 5;
    const int gid  = lane >> 2;
    const int tig  = lane & 3;
    const int wm   = (warp >> 2) * 64;
    const int wn   = (warp & 3) * 32;
    const int bm   = blockIdx.y * BM;
    const int bn   = blockIdx.x * BN;

    const int arow = tid >> 3;          // +p*32 rows
    const int acol = (tid & 7) << 2;
    const int brow = tid >> 5;          // +p*8 rows
    const int bcol = (tid & 31) << 2;

    const float* Ag = A  + (size_t)(bm + arow) * K + acol;
    const float* Bg = Bm + (size_t)brow * N + bn + bcol;

    float c[4][4][4];
    #pragma unroll
    for (int i = 0; i < 4; i++)
        #pragma unroll
        for (int j = 0; j < 4; j++)
            #pragma unroll
            for (int l = 0; l < 4; l++) c[i][j][l] = 0.f;

    const int ntiles = K / BK;
    float4 pa[4], pb[4];
    // prologue: load tile 0
    #pragma unroll
    for (int p = 0; p < 4; p++) pa[p] = *(const float4*)(Ag + (size_t)(p * 32) * K);
    #pragma unroll
    for (int p = 0; p < 4; p++) pb[p] = *(const float4*)(Bg + (size_t)(p * 8) * N);

    for (int t = 0; ; ) {
        // store (with tf32 rounding) to smem
        #pragma unroll
        for (int p = 0; p < 4; p++) {
            float4 v = pa[p];
            float4 o;
            o.x = __uint_as_float(tf32r(v.x)); o.y = __uint_as_float(tf32r(v.y));
            o.z = __uint_as_float(tf32r(v.z)); o.w = __uint_as_float(tf32r(v.w));
            *(float4*)&As[arow + p * 32][acol] = o;
        }
        #pragma unroll
        for (int p = 0; p < 4; p++) {
            float4 v = pb[p];
            float4 o;
            o.x = __uint_as_float(tf32r(v.x)); o.y = __uint_as_float(tf32r(v.y));
            o.z = __uint_as_float(tf32r(v.z)); o.w = __uint_as_float(tf32r(v.w));
            *(float4*)&Bs[brow + p * 8][bcol] = o;
        }
        __syncthreads();

        if (t + 1 < ntiles) {
            const int k0 = (t + 1) * BK;
            #pragma unroll
            for (int p = 0; p < 4; p++) pa[p] = *(const float4*)(Ag + (size_t)(p * 32) * K + k0);
            #pragma unroll
            for (int p = 0; p < 4; p++) pb[p] = *(const float4*)(Bg + (size_t)(k0 + p * 8) * N);
        }

        #pragma unroll
        for (int ks = 0; ks < 4; ks++) {
            const int kk = ks * 8;
            uint32_t af[4][4], bf[4][2];
            #pragma unroll
            for (int mt = 0; mt < 4; mt++) {
                const int r = wm + mt * 16 + gid;
                af[mt][0] = __float_as_uint(As[r    ][kk + tig]);
                af[mt][1] = __float_as_uint(As[r + 8][kk + tig]);
                af[mt][2] = __float_as_uint(As[r    ][kk + tig + 4]);
                af[mt][3] = __float_as_uint(As[r + 8][kk + tig + 4]);
            }
            #pragma unroll
            for (int nt = 0; nt < 4; nt++) {
                const int cc = wn + nt * 8 + gid;
                bf[nt][0] = __float_as_uint(Bs[kk + tig    ][cc]);
                bf[nt][1] = __float_as_uint(Bs[kk + tig + 4][cc]);
            }
            #pragma unroll
            for (int mt = 0; mt < 4; mt++)
                #pragma unroll
                for (int nt = 0; nt < 4; nt++)
                    mma_tf32(c[mt][nt], af[mt][0], af[mt][1], af[mt][2], af[mt][3],
                             bf[nt][0], bf[nt][1]);
        }

        if (++t == ntiles) break;
        __syncthreads();
    }

    #pragma unroll
    for (int mt = 0; mt < 4; mt++) {
        #pragma unroll
        for (int nt = 0; nt < 4; nt++) {
            const int col = bn + wn + nt * 8 + 2 * tig;
            #pragma unroll
            for (int h = 0; h < 2; h++) {
                const int r = bm + wm + mt * 16 + gid + h * 8;
                float v0 = c[mt][nt][2 * h], v1 = c[mt][nt][2 * h + 1];
                if (EPI == 1) {
                    v0 = fmaxf(v0 + bias[col], 0.f);
                    v1 = fmaxf(v1 + bias[col + 1], 0.f);
                } else if (EPI == 2) {
                    const size_t gi = (size_t)r * N + col;
                    v0 = v0 + bias[col]     + resid[gi];
                    v1 = v1 + bias[col + 1] + resid[gi + 1];
                }
                float2 o; o.x = v0; o.y = v1;
                *(float2*)&C[(size_t)r * N + col] = o;
            }
        }
    }
}

// ---------------- scores: S[b,q,t] = scale * Q[b,q,:].K[b,t,:] ------------------
// Strictly-upper tiles are skipped entirely (softmax never reads t > q).
__global__ __launch_bounds__(NT, 1)
void scores_tf32(const float* __restrict__ Q, const float* __restrict__ Kmat,
                 float* __restrict__ S)
{
    const int bm = blockIdx.y * BM;   // q tile
    const int bn = blockIdx.x * BN;   // t tile
    if (bn > bm) return;              // fully masked tile: skip (never read)

    const int b = blockIdx.z;
    __shared__ float Qs[BM][PADA];
    __shared__ float Ks[BM][PADA];

    const int tid  = threadIdx.x;
    const int lane = tid & 31;
    const int warp = tid >> 5;
    const int gid  = lane >> 2;
    const int tig  = lane & 3;
    const int wm   = (warp >> 2) * 64;
    const int wn   = (warp & 3) * 32;

    const int arow = tid >> 3;
    const int acol = (tid & 7) << 2;

    const float* Qg = Q    + (size_t)b * T_ * D_ + (size_t)(bm + arow) * D_ + acol;
    const float* Kg = Kmat + (size_t)b * T_ * D_ + (size_t)(bn + arow) * D_ + acol;
    float* Sb = S + (size_t)b * T_ * T_;

    float c[4][4][4];
    #pragma unroll
    for (int i = 0; i < 4; i++)
        #pragma unroll
        for (int j = 0; j < 4; j++)
            #pragma unroll
            for (int l = 0; l < 4; l++) c[i][j][l] = 0.f;

    const int ntiles = D_ / BK;
    float4 pa[4], pb[4];
    #pragma unroll
    for (int p = 0; p < 4; p++) pa[p] = *(const float4*)(Qg + (size_t)(p * 32) * D_);
    #pragma unroll
    for (int p = 0; p < 4; p++) pb[p] = *(const float4*)(Kg + (size_t)(p * 32) * D_);

    for (int t = 0; ; ) {
        #pragma unroll
        for (int p = 0; p < 4; p++) {
            float4 v = pa[p];
            float4 o;
            o.x = __uint_as_float(tf32r(v.x)); o.y = __uint_as_float(tf32r(v.y));
            o.z = __uint_as_float(tf32r(v.z)); o.w = __uint_as_float(tf32r(v.w));
            *(float4*)&Qs[arow + p * 32][acol] = o;
        }
        #pragma unroll
        for (int p = 0; p < 4; p++) {
            float4 v = pb[p];
            float4 o;
            o.x = __uint_as_float(tf32r(v.x)); o.y = __uint_as_float(tf32r(v.y));
            o.z = __uint_as_float(tf32r(v.z)); o.w = __uint_as_float(tf32r(v.w));
            *(float4*)&Ks[arow + p * 32][acol] = o;
        }
        __syncthreads();

        if (t + 1 < ntiles) {
            const int k0 = (t + 1) * BK;
            #pragma unroll
            for (int p = 0; p < 4; p++) pa[p] = *(const float4*)(Qg + (size_t)(p * 32) * D_ + k0);
            #pragma unroll
            for (int p = 0; p < 4; p++) pb[p] = *(const float4*)(Kg + (size_t)(p * 32) * D_ + k0);
        }

        #pragma unroll
        for (int ks = 0; ks < 4; ks++) {
            const int kk = ks * 8;
            uint32_t af[4][4], bf[4][2];
            #pragma unroll
            for (int mt = 0; mt < 4; mt++) {
                const int r = wm + mt * 16 + gid;
                af[mt][0] = __float_as_uint(Qs[r    ][kk + tig]);
                af[mt][1] = __float_as_uint(Qs[r + 8][kk + tig]);
                af[mt][2] = __float_as_uint(Qs[r    ][kk + tig + 4]);
                af[mt][3] = __float_as_uint(Qs[r + 8][kk + tig + 4]);
            }
            #pragma unroll
            for (int nt = 0; nt < 4; nt++) {
                const int cc = wn + nt * 8 + gid;
                bf[nt][0] = __float_as_uint(Ks[cc][kk + tig]);
                bf[nt][1] = __float_as_uint(Ks[cc][kk + tig + 4]);
            }
            #pragma unroll
            for (int mt = 0; mt < 4; mt++)
                #pragma unroll
                for (int nt = 0; nt < 4; nt++)
                    mma_tf32(c[mt][nt], af[mt][0], af[mt][1], af[mt][2], af[mt][3],
                             bf[nt][0], bf[nt][1]);
        }

        if (++t == ntiles) break;
        __syncthreads();
    }

    const float scale = 0.03125f;  // 1/sqrt(1024)
    #pragma unroll
    for (int mt = 0; mt < 4; mt++) {
        #pragma unroll
        for (int nt = 0; nt < 4; nt++) {
            const int col = bn + wn + nt * 8 + 2 * tig;
            #pragma unroll
            for (int h = 0; h < 2; h++) {
                const int q = bm + wm + mt * 16 + gid + h * 8;
                float2 o;
                o.x = c[mt][nt][2 * h] * scale;
                o.y = c[mt][nt][2 * h + 1] * scale;
                *(float2*)&Sb[(size_t)q * T_ + col] = o;
            }
        }
    }
}

// ---------------- causal row softmax: reads [0,q], zero-fills (q, pad128] -------
__global__ void softmax_kernel(float* __restrict__ S)
{
    const int row = blockIdx.x;           // 0..M_-1
    const int b = row >> 11;
    const int q = row & (T_ - 1);
    float* r = S + (size_t)b * T_ * T_ + (size_t)q * T_;
    const int n = q + 1;
    const int pad = ((q >> 7) + 1) << 7;  // round_up(q+1, 128)

    float m = -1e30f;
    for (int i = threadIdx.x; i < n; i += 256) m = fmaxf(m, r[i]);
    #pragma unroll
    for (int o = 16; o; o >>= 1) m = fmaxf(m, __shfl_xor_sync(0xffffffffu, m, o));
    __shared__ float shm[8], shs[8];
    const int w = threadIdx.x >> 5;
    if ((threadIdx.x & 31) == 0) shm[w] = m;
    __syncthreads();
    m = shm[0];
    #pragma unroll
    for (int i = 1; i < 8; i++) m = fmaxf(m, shm[i]);

    float s = 0.f;
    for (int i = threadIdx.x; i < n; i += 256) {
        float e = __expf(r[i] - m);
        r[i] = e;
        s += e;
    }
    #pragma unroll
    for (int o = 16; o; o >>= 1) s += __shfl_xor_sync(0xffffffffu, s, o);
    if ((threadIdx.x & 31) == 0) shs[w] = s;
    __syncthreads();
    s = 0.f;
    #pragma unroll
    for (int i = 0; i < 8; i++) s += shs[i];
    const float inv = 1.0f / s;
    for (int i = threadIdx.x; i < n; i += 256) r[i] *= inv;
    for (int i = n + threadIdx.x; i < pad; i += 256) r[i] = 0.f;
}

// ---------------- Y = P @ V + x (causal k-bound) --------------------------------
__global__ __launch_bounds__(NT, 1)
void av_tf32(const float* __restrict__ P, const float* __restrict__ V,
             const float* __restrict__ x, float* __restrict__ Y)
{
    const int b  = blockIdx.z;
    const int bm = blockIdx.y * BM;   // q tile
    const int bn = blockIdx.x * BN;   // d tile
    __shared__ float As[BM][PADA];
    __shared__ float Bs[BK][PADB];

    const int tid  = threadIdx.x;
    const int lane = tid & 31;
    const int warp = tid >> 5;
    const int gid  = lane >> 2;
    const int tig  = lane & 3;
    const int wm   = (warp >> 2) * 64;
    const int wn   = (warp & 3) * 32;

    const int arow = tid >> 3;
    const int acol = (tid & 7) << 2;
    const int brow = tid >> 5;
    const int bcol = (tid & 31) << 2;

    const float* Ag = P + (size_t)b * T_ * T_ + (size_t)(bm + arow) * T_ + acol;
    const float* Bg = V + (size_t)b * T_ * D_ + (size_t)brow * D_ + bn + bcol;

    float c[4][4][4];
    #pragma unroll
    for (int i = 0; i < 4; i++)
        #pragma unroll
        for (int j = 0; j < 4; j++)
            #pragma unroll
            for (int l = 0; l < 4; l++) c[i][j][l] = 0.f;

    const int ntiles = (bm + BM) / BK;   // causal: P zero beyond q within last tile
    float4 pa[4], pb[4];
    #pragma unroll
    for (int p = 0; p < 4; p++) pa[p] = *(const float4*)(Ag + (size_t)(p * 32) * T_);
    #pragma unroll
    for (int p = 0; p < 4; p++) pb[p] = *(const float4*)(Bg + (size_t)(p * 8) * D_);

    for (int t = 0; ; ) {
        #pragma unroll
        for (int p = 0; p < 4; p++) {
            float4 v = pa[p];
            float4 o;
            o.x = __uint_as_float(tf32r(v.x)); o.y = __uint_as_float(tf32r(v.y));
            o.z = __uint_as_float(tf32r(v.z)); o.w = __uint_as_float(tf32r(v.w));
            *(float4*)&As[arow + p * 32][acol] = o;
        }
        #pragma unroll
        for (int p = 0; p < 4; p++) {
            float4 v = pb[p];
            float4 o;
            o.x = __uint_as_float(tf32r(v.x)); o.y = __uint_as_float(tf32r(v.y));
            o.z = __uint_as_float(tf32r(v.z)); o.w = __uint_as_float(tf32r(v.w));
            *(float4*)&Bs[brow + p * 8][bcol] = o;
        }
        __syncthreads();

        if (t + 1 < ntiles) {
            const int k0 = (t + 1) * BK;
            #pragma unroll
            for (int p = 0; p < 4; p++) pa[p] = *(const float4*)(Ag + (size_t)(p * 32) * T_ + k0);
            #pragma unroll
            for (int p = 0; p < 4; p++) pb[p] = *(const float4*)(Bg + (size_t)(k0 + p * 8) * D_);
        }

        #pragma unroll
        for (int ks = 0; ks < 4; ks++) {
            const int kk = ks * 8;
            uint32_t af[4][4], bf[4][2];
            #pragma unroll
            for (int mt = 0; mt < 4; mt++) {
                const int r = wm + mt * 16 + gid;
                af[mt][0] = __float_as_uint(As[r    ][kk + tig]);
                af[mt][1] = __float_as_uint(As[r + 8][kk + tig]);
                af[mt][2] = __float_as_uint(As[r    ][kk + tig + 4]);
                af[mt][3] = __float_as_uint(As[r + 8][kk + tig + 4]);
            }
            #pragma unroll
            for (int nt = 0; nt < 4; nt++) {
                const int cc = wn + nt * 8 + gid;
                bf[nt][0] = __float_as_uint(Bs[kk + tig    ][cc]);
                bf[nt][1] = __float_as_uint(Bs[kk + tig + 4][cc]);
            }
            #pragma unroll
            for (int mt = 0; mt < 4; mt++)
                #pragma unroll
                for (int nt = 0; nt < 4; nt++)
                    mma_tf32(c[mt][nt], af[mt][0], af[mt][1], af[mt][2], af[mt][3],
                             bf[nt][0], bf[nt][1]);
        }

        if (++t == ntiles) break;
        __syncthreads();
    }

    #pragma unroll
    for (int mt = 0; mt < 4; mt++) {
        #pragma unroll
        for (int nt = 0; nt < 4; nt++) {
            const int col = bn + wn + nt * 8 + 2 * tig;
            #pragma unroll
            for (int h = 0; h < 2; h++) {
                const int q = bm + wm + mt * 16 + gid + h * 8;
                const size_t gi = ((size_t)(b * T_ + q)) * D_ + col;
                float2 xv = *(const float2*)&x[gi];
                float2 o;
                o.x = c[mt][nt][2 * h]     + xv.x;
                o.y = c[mt][nt][2 * h + 1] + xv.y;
                *(float2*)&Y[gi] = o;
            }
        }
    }
}

// ---------------- launch --------------------------------------------------------
extern "C" void kernel_launch(void* const* d_in, const int* in_sizes, int n_in,
                              void* d_out, int out_size)
{
    const float* x   = (const float*)d_in[0];
    const float* g1  = (const float*)d_in[1];
    const float* be1 = (const float*)d_in[2];
    const float* wq  = (const float*)d_in[3];
    const float* wk  = (const float*)d_in[4];
    const float* wv  = (const float*)d_in[5];
    const float* g2  = (const float*)d_in[6];
    const float* be2 = (const float*)d_in[7];
    const float* W1  = (const float*)d_in[8];
    const float* b1  = (const float*)d_in[9];
    const float* W2  = (const float*)d_in[10];
    const float* b2  = (const float*)d_in[11];
    float* out = (float*)d_out;

    float *p_h, *p_q, *p_k, *p_v, *p_s, *p_y, *p_h2, *p_m1;
    cudaGetSymbolAddress((void**)&p_h,  g_h);
    cudaGetSymbolAddress((void**)&p_q,  g_q);
    cudaGetSymbolAddress((void**)&p_k,  g_k);
    cudaGetSymbolAddress((void**)&p_v,  g_v);
    cudaGetSymbolAddress((void**)&p_s,  g_s);
    cudaGetSymbolAddress((void**)&p_y,  g_y);
    cudaGetSymbolAddress((void**)&p_h2, g_h2);
    cudaGetSymbolAddress((void**)&p_m1, g_m1);

    const dim3 gemm_grid(D_ / BN, M_ / BM);        // (8, 64)
    const dim3 sc_grid(T_ / BN, T_ / BM, B_);      // (16, 16, 4)
    const dim3 av_grid(D_ / BN, T_ / BM, B_);      // (8, 16, 4)

    ln_kernel<<<M_, 256>>>(x, g1, be1, p_h);
    gemm_tf32<0><<<gemm_grid, NT>>>(p_h, wq, p_q, nullptr, nullptr, M_, D_, D_);
    gemm_tf32<0><<<gemm_grid, NT>>>(p_h, wk, p_k, nullptr, nullptr, M_, D_, D_);
    gemm_tf32<0><<<gemm_grid, NT>>>(p_h, wv, p_v, nullptr, nullptr, M_, D_, D_);
    scores_tf32<<<sc_grid, NT>>>(p_q, p_k, p_s);
    softmax_kernel<<<M_, 256>>>(p_s);
    av_tf32<<<av_grid, NT>>>(p_s, p_v, x, p_y);
    ln_kernel<<<M_, 256>>>(p_y, g2, be2, p_h2);
    gemm_tf32<1><<<gemm_grid, NT>>>(p_h2, W1, p_m1, b1, nullptr, M_, D_, D_);
    gemm_tf32<2><<<gemm_grid, NT>>>(p_m1, W2, out, b2, p_y, M_, D_, D_);
}

// round 3
// speedup vs baseline: 3.4347x; 1.0767x over previous
#include <cuda_runtime.h>
#include <math.h>
#include <stdint.h>

#define B_ 4
#define T_ 2048
#define D_ 1024
#define M_ (B_*T_)

#define NT 256
#define BM 128
#define BN 128
#define BK 32
#define PADA 36       // floats, row stride for [rows][BK] tiles (144B, 16B-aligned)
#define PADB 132      // floats, row stride for [BK][cols] tiles (528B, 16B-aligned)
#define STAGES 3

#define A_ELEMS (BM*PADA)   // 4608 floats / stage
#define B_ELEMS (BK*PADB)   // 4224 floats / stage

// ---------------- scratch -------------------------------------------------------
__device__ float g_h [M_*D_];
__device__ float g_q [M_*D_];
__device__ float g_k [M_*D_];
__device__ float g_v [M_*D_];
__device__ float g_s [(size_t)B_*T_*T_];
__device__ float g_y [M_*D_];
__device__ float g_h2[M_*D_];
__device__ float g_m1[M_*D_];
__device__ float g_wq[D_*D_];
__device__ float g_wk[D_*D_];
__device__ float g_wv[D_*D_];
__device__ float g_w1[D_*D_];
__device__ float g_w2[D_*D_];

// ---------------- helpers -------------------------------------------------------
__device__ __forceinline__ uint32_t tf32r(float x) {
    uint32_t y;
    asm("cvt.rna.tf32.f32 %0, %1;" : "=r"(y) : "f"(x));
    return y;
}
__device__ __forceinline__ float tf32rf(float x) { return __uint_as_float(tf32r(x)); }

__device__ __forceinline__ void cpa16(float* s, const float* g) {
    uint32_t sa = (uint32_t)__cvta_generic_to_shared(s);
    asm volatile("cp.async.cg.shared.global [%0], [%1], 16;" :: "r"(sa), "l"(g));
}
#define CP_COMMIT()  asm volatile("cp.async.commit_group;")
#define CP_WAIT1()   asm volatile("cp.async.wait_group 1;")

__device__ __forceinline__ void mma_tf32(float c[4], uint32_t a0, uint32_t a1,
                                         uint32_t a2, uint32_t a3,
                                         uint32_t b0, uint32_t b1)
{
    asm volatile(
        "mma.sync.aligned.m16n8k8.row.col.f32.tf32.tf32.f32 "
        "{%0,%1,%2,%3}, {%4,%5,%6,%7}, {%8,%9}, {%0,%1,%2,%3};"
        : "+f"(c[0]), "+f"(c[1]), "+f"(c[2]), "+f"(c[3])
        : "r"(a0), "r"(a1), "r"(a2), "r"(a3), "r"(b0), "r"(b1));
}

// ---------------- round weights to tf32 (vectorized) -----------------------------
__global__ void roundw_kernel(const float* __restrict__ w, float* __restrict__ o)
{
    const int i = (blockIdx.x * 256 + threadIdx.x) * 4;   // grid covers D_*D_
    float4 v = *(const float4*)(w + i);
    float4 r;
    r.x = tf32rf(v.x); r.y = tf32rf(v.y); r.z = tf32rf(v.z); r.w = tf32rf(v.w);
    *(float4*)(o + i) = r;
}

// ---------------- LayerNorm (reference's buggy LN), output rounded to tf32 ------
__global__ void ln_kernel(const float* __restrict__ x, const float* __restrict__ gamma,
                          const float* __restrict__ beta, float* __restrict__ out)
{
    const int row = blockIdx.x;
    const float* xr = x + (size_t)row * D_;
    float s = 0.f, ss = 0.f;
    for (int i = threadIdx.x; i < D_; i += 256) {
        float v = xr[i];
        s += v; ss += v * v;
    }
    #pragma unroll
    for (int o = 16; o; o >>= 1) {
        s  += __shfl_xor_sync(0xffffffffu, s, o);
        ss += __shfl_xor_sync(0xffffffffu, ss, o);
    }
    __shared__ float sh_s[8], sh_ss[8];
    const int w = threadIdx.x >> 5;
    if ((threadIdx.x & 31) == 0) { sh_s[w] = s; sh_ss[w] = ss; }
    __syncthreads();
    s = 0.f; ss = 0.f;
    #pragma unroll
    for (int i = 0; i < 8; i++) { s += sh_s[i]; ss += sh_ss[i]; }
    const float mu  = s * (1.0f / D_);
    const float var = (ss - (float)D_ * mu * mu) * (1.0f / (float)(D_ - 1));
    const float c   = mu * rsqrtf(var);
    float* outr = out + (size_t)row * D_;
    for (int i = threadIdx.x; i < D_; i += 256)
        outr[i] = tf32rf((xr[i] - c) * gamma[i] + beta[i]);
}

// ---------------- tf32 pipelined GEMM: C = A[M,K] @ B[K,N] (+epilogue) ----------
// EPI 0: tf32(acc); 1: tf32(relu(acc+bias)); 2: acc+bias+resid (full fp32)
template<int EPI>
__global__ __launch_bounds__(NT, 1)
void gemm_tf32(const float* __restrict__ A, const float* __restrict__ Bm,
               float* __restrict__ C, const float* __restrict__ bias,
               const float* __restrict__ resid, int M, int N, int K)
{
    extern __shared__ float sm[];
    float* As = sm;                       // [STAGES][BM][PADA]
    float* Bs = sm + STAGES * A_ELEMS;    // [STAGES][BK][PADB]

    const int tid  = threadIdx.x;
    const int lane = tid & 31;
    const int warp = tid >> 5;
    const int gid  = lane >> 2;
    const int tig  = lane & 3;
    const int wm   = (warp >> 2) * 64;
    const int wn   = (warp & 3) * 32;
    const int bm   = blockIdx.y * BM;
    const int bn   = blockIdx.x * BN;

    const int arow = tid >> 3;
    const int acol = (tid & 7) << 2;
    const int brow = tid >> 5;
    const int bcol = (tid & 31) << 2;

    const float* Ag = A  + (size_t)(bm + arow) * K + acol;
    const float* Bg = Bm + (size_t)brow * N + bn + bcol;

    float c[4][4][4];
    #pragma unroll
    for (int i = 0; i < 4; i++)
        #pragma unroll
        for (int j = 0; j < 4; j++)
            #pragma unroll
            for (int l = 0; l < 4; l++) c[i][j][l] = 0.f;

    const int ntiles = K / BK;

    #pragma unroll
    for (int s = 0; s < STAGES - 1; s++) {
        const int k0 = s * BK;
        #pragma unroll
        for (int p = 0; p < 4; p++)
            cpa16(As + (s*BM + arow + p*32)*PADA + acol, Ag + (size_t)(p*32)*K + k0);
        #pragma unroll
        for (int p = 0; p < 4; p++)
            cpa16(Bs + (s*BK + brow + p*8)*PADB + bcol, Bg + (size_t)(k0 + p*8)*N);
        CP_COMMIT();
    }

    for (int t = 0; t < ntiles; t++) {
        CP_WAIT1();
        __syncthreads();
        const int tn = t + STAGES - 1;
        if (tn < ntiles) {
            const int s = tn % STAGES, k0 = tn * BK;
            #pragma unroll
            for (int p = 0; p < 4; p++)
                cpa16(As + (s*BM + arow + p*32)*PADA + acol, Ag + (size_t)(p*32)*K + k0);
            #pragma unroll
            for (int p = 0; p < 4; p++)
                cpa16(Bs + (s*BK + brow + p*8)*PADB + bcol, Bg + (size_t)(k0 + p*8)*N);
        }
        CP_COMMIT();

        const float* Ast = As + (t % STAGES) * A_ELEMS;
        const float* Bst = Bs + (t % STAGES) * B_ELEMS;
        #pragma unroll
        for (int ks = 0; ks < 4; ks++) {
            const int kk = ks * 8;
            uint32_t af[4][4], bf[4][2];
            #pragma unroll
            for (int mt = 0; mt < 4; mt++) {
                const int r = wm + mt * 16 + gid;
                af[mt][0] = __float_as_uint(Ast[(r    )*PADA + kk + tig]);
                af[mt][1] = __float_as_uint(Ast[(r + 8)*PADA + kk + tig]);
                af[mt][2] = __float_as_uint(Ast[(r    )*PADA + kk + tig + 4]);
                af[mt][3] = __float_as_uint(Ast[(r + 8)*PADA + kk + tig + 4]);
            }
            #pragma unroll
            for (int nt = 0; nt < 4; nt++) {
                const int cc = wn + nt * 8 + gid;
                bf[nt][0] = __float_as_uint(Bst[(kk + tig    )*PADB + cc]);
                bf[nt][1] = __float_as_uint(Bst[(kk + tig + 4)*PADB + cc]);
            }
            #pragma unroll
            for (int mt = 0; mt < 4; mt++)
                #pragma unroll
                for (int nt = 0; nt < 4; nt++)
                    mma_tf32(c[mt][nt], af[mt][0], af[mt][1], af[mt][2], af[mt][3],
                             bf[nt][0], bf[nt][1]);
        }
    }

    #pragma unroll
    for (int mt = 0; mt < 4; mt++) {
        #pragma unroll
        for (int nt = 0; nt < 4; nt++) {
            const int col = bn + wn + nt * 8 + 2 * tig;
            #pragma unroll
            for (int h = 0; h < 2; h++) {
                const int r = bm + wm + mt * 16 + gid + h * 8;
                float v0 = c[mt][nt][2 * h], v1 = c[mt][nt][2 * h + 1];
                if (EPI == 0) {
                    v0 = tf32rf(v0); v1 = tf32rf(v1);
                } else if (EPI == 1) {
                    v0 = tf32rf(fmaxf(v0 + bias[col], 0.f));
                    v1 = tf32rf(fmaxf(v1 + bias[col + 1], 0.f));
                } else {
                    const size_t gi = (size_t)r * N + col;
                    v0 = v0 + bias[col]     + resid[gi];
                    v1 = v1 + bias[col + 1] + resid[gi + 1];
                }
                float2 o; o.x = v0; o.y = v1;
                *(float2*)&C[(size_t)r * N + col] = o;
            }
        }
    }
}

// ---------------- scores: S = scale * Q K^T (lower-triangle tiles only) ---------
__global__ __launch_bounds__(NT, 1)
void scores_tf32(const float* __restrict__ Q, const float* __restrict__ Kmat,
                 float* __restrict__ S)
{
    const int bm = blockIdx.y * BM;
    const int bn = blockIdx.x * BN;
    if (bn > bm) return;

    extern __shared__ float sm[];
    float* Qs = sm;                       // [STAGES][BM][PADA]
    float* Ks = sm + STAGES * A_ELEMS;    // [STAGES][BM][PADA]

    const int b = blockIdx.z;
    const int tid  = threadIdx.x;
    const int lane = tid & 31;
    const int warp = tid >> 5;
    const int gid  = lane >> 2;
    const int tig  = lane & 3;
    const int wm   = (warp >> 2) * 64;
    const int wn   = (warp & 3) * 32;

    const int arow = tid >> 3;
    const int acol = (tid & 7) << 2;

    const float* Qg = Q    + (size_t)b * T_ * D_ + (size_t)(bm + arow) * D_ + acol;
    const float* Kg = Kmat + (size_t)b * T_ * D_ + (size_t)(bn + arow) * D_ + acol;
    float* Sb = S + (size_t)b * T_ * T_;

    float c[4][4][4];
    #pragma unroll
    for (int i = 0; i < 4; i++)
        #pragma unroll
        for (int j = 0; j < 4; j++)
            #pragma unroll
            for (int l = 0; l < 4; l++) c[i][j][l] = 0.f;

    const int ntiles = D_ / BK;

    #pragma unroll
    for (int s = 0; s < STAGES - 1; s++) {
        const int k0 = s * BK;
        #pragma unroll
        for (int p = 0; p < 4; p++)
            cpa16(Qs + (s*BM + arow + p*32)*PADA + acol, Qg + (size_t)(p*32)*D_ + k0);
        #pragma unroll
        for (int p = 0; p < 4; p++)
            cpa16(Ks + (s*BM + arow + p*32)*PADA + acol, Kg + (size_t)(p*32)*D_ + k0);
        CP_COMMIT();
    }

    for (int t = 0; t < ntiles; t++) {
        CP_WAIT1();
        __syncthreads();
        const int tn = t + STAGES - 1;
        if (tn < ntiles) {
            const int s = tn % STAGES, k0 = tn * BK;
            #pragma unroll
            for (int p = 0; p < 4; p++)
                cpa16(Qs + (s*BM + arow + p*32)*PADA + acol, Qg + (size_t)(p*32)*D_ + k0);
            #pragma unroll
            for (int p = 0; p < 4; p++)
                cpa16(Ks + (s*BM + arow + p*32)*PADA + acol, Kg + (size_t)(p*32)*D_ + k0);
        }
        CP_COMMIT();

        const float* Qst = Qs + (t % STAGES) * A_ELEMS;
        const float* Kst = Ks + (t % STAGES) * A_ELEMS;
        #pragma unroll
        for (int ks = 0; ks < 4; ks++) {
            const int kk = ks * 8;
            uint32_t af[4][4], bf[4][2];
            #pragma unroll
            for (int mt = 0; mt < 4; mt++) {
                const int r = wm + mt * 16 + gid;
                af[mt][0] = __float_as_uint(Qst[(r    )*PADA + kk + tig]);
                af[mt][1] = __float_as_uint(Qst[(r + 8)*PADA + kk + tig]);
                af[mt][2] = __float_as_uint(Qst[(r    )*PADA + kk + tig + 4]);
                af[mt][3] = __float_as_uint(Qst[(r + 8)*PADA + kk + tig + 4]);
            }
            #pragma unroll
            for (int nt = 0; nt < 4; nt++) {
                const int cc = wn + nt * 8 + gid;
                bf[nt][0] = __float_as_uint(Kst[cc*PADA + kk + tig]);
                bf[nt][1] = __float_as_uint(Kst[cc*PADA + kk + tig + 4]);
            }
            #pragma unroll
            for (int mt = 0; mt < 4; mt++)
                #pragma unroll
                for (int nt = 0; nt < 4; nt++)
                    mma_tf32(c[mt][nt], af[mt][0], af[mt][1], af[mt][2], af[mt][3],
                             bf[nt][0], bf[nt][1]);
        }
    }

    const float scale = 0.03125f;
    #pragma unroll
    for (int mt = 0; mt < 4; mt++) {
        #pragma unroll
        for (int nt = 0; nt < 4; nt++) {
            const int col = bn + wn + nt * 8 + 2 * tig;
            #pragma unroll
            for (int h = 0; h < 2; h++) {
                const int q = bm + wm + mt * 16 + gid + h * 8;
                float2 o;
                o.x = c[mt][nt][2 * h] * scale;
                o.y = c[mt][nt][2 * h + 1] * scale;
                *(float2*)&Sb[(size_t)q * T_ + col] = o;
            }
        }
    }
}

// ---------------- causal softmax, P rounded to tf32, zero-fill tile pad ---------
__global__ void softmax_kernel(float* __restrict__ S)
{
    const int row = blockIdx.x;
    const int b = row >> 11;
    const int q = row & (T_ - 1);
    float* r = S + (size_t)b * T_ * T_ + (size_t)q * T_;
    const int n = q + 1;
    const int pad = ((q >> 7) + 1) << 7;

    float m = -1e30f;
    for (int i = threadIdx.x; i < n; i += 256) m = fmaxf(m, r[i]);
    #pragma unroll
    for (int o = 16; o; o >>= 1) m = fmaxf(m, __shfl_xor_sync(0xffffffffu, m, o));
    __shared__ float shm[8], shs[8];
    const int w = threadIdx.x >> 5;
    if ((threadIdx.x & 31) == 0) shm[w] = m;
    __syncthreads();
    m = shm[0];
    #pragma unroll
    for (int i = 1; i < 8; i++) m = fmaxf(m, shm[i]);

    float s = 0.f;
    for (int i = threadIdx.x; i < n; i += 256) {
        float e = __expf(r[i] - m);
        r[i] = e;
        s += e;
    }
    #pragma unroll
    for (int o = 16; o; o >>= 1) s += __shfl_xor_sync(0xffffffffu, s, o);
    if ((threadIdx.x & 31) == 0) shs[w] = s;
    __syncthreads();
    s = 0.f;
    #pragma unroll
    for (int i = 0; i < 8; i++) s += shs[i];
    const float inv = 1.0f / s;
    for (int i = threadIdx.x; i < n; i += 256) r[i] = tf32rf(r[i] * inv);
    for (int i = n + threadIdx.x; i < pad; i += 256) r[i] = 0.f;
}

// ---------------- Y = P @ V + x (causal k-bound), fp32 out ----------------------
__global__ __launch_bounds__(NT, 1)
void av_tf32(const float* __restrict__ P, const float* __restrict__ V,
             const float* __restrict__ x, float* __restrict__ Y)
{
    extern __shared__ float sm[];
    float* As = sm;
    float* Bs = sm + STAGES * A_ELEMS;

    const int b  = blockIdx.z;
    const int bm = blockIdx.y * BM;
    const int bn = blockIdx.x * BN;

    const int tid  = threadIdx.x;
    const int lane = tid & 31;
    const int warp = tid >> 5;
    const int gid  = lane >> 2;
    const int tig  = lane & 3;
    const int wm   = (warp >> 2) * 64;
    const int wn   = (warp & 3) * 32;

    const int arow = tid >> 3;
    const int acol = (tid & 7) << 2;
    const int brow = tid >> 5;
    const int bcol = (tid & 31) << 2;

    const float* Ag = P + (size_t)b * T_ * T_ + (size_t)(bm + arow) * T_ + acol;
    const float* Bg = V + (size_t)b * T_ * D_ + (size_t)brow * D_ + bn + bcol;

    float c[4][4][4];
    #pragma unroll
    for (int i = 0; i < 4; i++)
        #pragma unroll
        for (int j = 0; j < 4; j++)
            #pragma unroll
            for (int l = 0; l < 4; l++) c[i][j][l] = 0.f;

    const int ntiles = (bm + BM) / BK;   // >= 4

    #pragma unroll
    for (int s = 0; s < STAGES - 1; s++) {
        const int k0 = s * BK;
        #pragma unroll
        for (int p = 0; p < 4; p++)
            cpa16(As + (s*BM + arow + p*32)*PADA + acol, Ag + (size_t)(p*32)*T_ + k0);
        #pragma unroll
        for (int p = 0; p < 4; p++)
            cpa16(Bs + (s*BK + brow + p*8)*PADB + bcol, Bg + (size_t)(k0 + p*8)*D_);
        CP_COMMIT();
    }

    for (int t = 0; t < ntiles; t++) {
        CP_WAIT1();
        __syncthreads();
        const int tn = t + STAGES - 1;
        if (tn < ntiles) {
            const int s = tn % STAGES, k0 = tn * BK;
            #pragma unroll
            for (int p = 0; p < 4; p++)
                cpa16(As + (s*BM + arow + p*32)*PADA + acol, Ag + (size_t)(p*32)*T_ + k0);
            #pragma unroll
            for (int p = 0; p < 4; p++)
                cpa16(Bs + (s*BK + brow + p*8)*PADB + bcol, Bg + (size_t)(k0 + p*8)*D_);
        }
        CP_COMMIT();

        const float* Ast = As + (t % STAGES) * A_ELEMS;
        const float* Bst = Bs + (t % STAGES) * B_ELEMS;
        #pragma unroll
        for (int ks = 0; ks < 4; ks++) {
            const int kk = ks * 8;
            uint32_t af[4][4], bf[4][2];
            #pragma unroll
            for (int mt = 0; mt < 4; mt++) {
                const int r = wm + mt * 16 + gid;
                af[mt][0] = __float_as_uint(Ast[(r    )*PADA + kk + tig]);
                af[mt][1] = __float_as_uint(Ast[(r + 8)*PADA + kk + tig]);
                af[mt][2] = __float_as_uint(Ast[(r    )*PADA + kk + tig + 4]);
                af[mt][3] = __float_as_uint(Ast[(r + 8)*PADA + kk + tig + 4]);
            }
            #pragma unroll
            for (int nt = 0; nt < 4; nt++) {
                const int cc = wn + nt * 8 + gid;
                bf[nt][0] = __float_as_uint(Bst[(kk + tig    )*PADB + cc]);
                bf[nt][1] = __float_as_uint(Bst[(kk + tig + 4)*PADB + cc]);
            }
            #pragma unroll
            for (int mt = 0; mt < 4; mt++)
                #pragma unroll
                for (int nt = 0; nt < 4; nt++)
                    mma_tf32(c[mt][nt], af[mt][0], af[mt][1], af[mt][2], af[mt][3],
                             bf[nt][0], bf[nt][1]);
        }
    }

    #pragma unroll
    for (int mt = 0; mt < 4; mt++) {
        #pragma unroll
        for (int nt = 0; nt < 4; nt++) {
            const int col = bn + wn + nt * 8 + 2 * tig;
            #pragma unroll
            for (int h = 0; h < 2; h++) {
                const int q = bm + wm + mt * 16 + gid + h * 8;
                const size_t gi = ((size_t)(b * T_ + q)) * D_ + col;
                float2 xv = *(const float2*)&x[gi];
                float2 o;
                o.x = c[mt][nt][2 * h]     + xv.x;
                o.y = c[mt][nt][2 * h + 1] + xv.y;
                *(float2*)&Y[gi] = o;
            }
        }
    }
}

// ---------------- launch --------------------------------------------------------
extern "C" void kernel_launch(void* const* d_in, const int* in_sizes, int n_in,
                              void* d_out, int out_size)
{
    const float* x   = (const float*)d_in[0];
    const float* g1  = (const float*)d_in[1];
    const float* be1 = (const float*)d_in[2];
    const float* wq  = (const float*)d_in[3];
    const float* wk  = (const float*)d_in[4];
    const float* wv  = (const float*)d_in[5];
    const float* g2  = (const float*)d_in[6];
    const float* be2 = (const float*)d_in[7];
    const float* W1  = (const float*)d_in[8];
    const float* b1  = (const float*)d_in[9];
    const float* W2  = (const float*)d_in[10];
    const float* b2  = (const float*)d_in[11];
    float* out = (float*)d_out;

    float *p_h, *p_q, *p_k, *p_v, *p_s, *p_y, *p_h2, *p_m1;
    float *p_wq, *p_wk, *p_wv, *p_w1, *p_w2;
    cudaGetSymbolAddress((void**)&p_h,  g_h);
    cudaGetSymbolAddress((void**)&p_q,  g_q);
    cudaGetSymbolAddress((void**)&p_k,  g_k);
    cudaGetSymbolAddress((void**)&p_v,  g_v);
    cudaGetSymbolAddress((void**)&p_s,  g_s);
    cudaGetSymbolAddress((void**)&p_y,  g_y);
    cudaGetSymbolAddress((void**)&p_h2, g_h2);
    cudaGetSymbolAddress((void**)&p_m1, g_m1);
    cudaGetSymbolAddress((void**)&p_wq, g_wq);
    cudaGetSymbolAddress((void**)&p_wk, g_wk);
    cudaGetSymbolAddress((void**)&p_wv, g_wv);
    cudaGetSymbolAddress((void**)&p_w1, g_w1);
    cudaGetSymbolAddress((void**)&p_w2, g_w2);

    const size_t smem_gemm = (size_t)STAGES * (A_ELEMS + B_ELEMS) * 4;  // 105984
    const size_t smem_sc   = (size_t)STAGES * (2 * A_ELEMS) * 4;        // 110592

    cudaFuncSetAttribute(gemm_tf32<0>, cudaFuncAttributeMaxDynamicSharedMemorySize, (int)smem_gemm);
    cudaFuncSetAttribute(gemm_tf32<1>, cudaFuncAttributeMaxDynamicSharedMemorySize, (int)smem_gemm);
    cudaFuncSetAttribute(gemm_tf32<2>, cudaFuncAttributeMaxDynamicSharedMemorySize, (int)smem_gemm);
    cudaFuncSetAttribute(scores_tf32,  cudaFuncAttributeMaxDynamicSharedMemorySize, (int)smem_sc);
    cudaFuncSetAttribute(av_tf32,      cudaFuncAttributeMaxDynamicSharedMemorySize, (int)smem_gemm);

    const dim3 gemm_grid(D_ / BN, M_ / BM);
    const dim3 sc_grid(T_ / BN, T_ / BM, B_);
    const dim3 av_grid(D_ / BN, T_ / BM, B_);
    const int rw_grid = (D_ * D_) / (256 * 4);

    roundw_kernel<<<rw_grid, 256>>>(wq, p_wq);
    roundw_kernel<<<rw_grid, 256>>>(wk, p_wk);
    roundw_kernel<<<rw_grid, 256>>>(wv, p_wv);
    roundw_kernel<<<rw_grid, 256>>>(W1, p_w1);
    roundw_kernel<<<rw_grid, 256>>>(W2, p_w2);

    ln_kernel<<<M_, 256>>>(x, g1, be1, p_h);
    gemm_tf32<0><<<gemm_grid, NT, smem_gemm>>>(p_h, p_wq, p_q, nullptr, nullptr, M_, D_, D_);
    gemm_tf32<0><<<gemm_grid, NT, smem_gemm>>>(p_h, p_wk, p_k, nullptr, nullptr, M_, D_, D_);
    gemm_tf32<0><<<gemm_grid, NT, smem_gemm>>>(p_h, p_wv, p_v, nullptr, nullptr, M_, D_, D_);
    scores_tf32<<<sc_grid, NT, smem_sc>>>(p_q, p_k, p_s);
    softmax_kernel<<<M_, 256>>>(p_s);
    av_tf32<<<av_grid, NT, smem_gemm>>>(p_s, p_v, x, p_y);
    ln_kernel<<<M_, 256>>>(p_y, g2, be2, p_h2);
    gemm_tf32<1><<<gemm_grid, NT, smem_gemm>>>(p_h2, p_w1, p_m1, b1, nullptr, M_, D_, D_);
    gemm_tf32<2><<<gemm_grid, NT, smem_gemm>>>(p_m1, p_w2, out, b2, p_y, M_, D_, D_);
}

// round 5
// speedup vs baseline: 7.2905x; 2.1226x over previous
#include <cuda_runtime.h>
#include <cuda_fp16.h>
#include <math.h>
#include <stdint.h>

#define B_ 4
#define T_ 2048
#define D_ 1024
#define M_ (B_*T_)

#define NT 256
#define BM 128
#define BN 128
#define BK 32              // halves per k-chunk
#define LDHS 40            // halves per smem row (80 B stride)
#define TILE_B (128*LDHS*2)     // 10240 B per operand tile
#define STAGE_B (2*TILE_B)      // 20480 B
#define NSTAGE 3
#define SMEM_B (NSTAGE*STAGE_B) // 61440 B

// ---------------- scratch ------------------------------------------------------
__device__ __half g_h  [M_*D_];
__device__ __half g_q  [M_*D_];
__device__ __half g_k  [M_*D_];
__device__ __half g_v  [M_*D_];
__device__ __half g_vt [(size_t)B_*D_*T_];
__device__ __half g_p  [(size_t)B_*T_*T_];
__device__ float  g_s  [(size_t)B_*T_*T_];
__device__ float  g_y  [M_*D_];
__device__ __half g_h2 [M_*D_];
__device__ __half g_m1 [M_*D_];
__device__ __half g_wqt[D_*D_];
__device__ __half g_wkt[D_*D_];
__device__ __half g_wvt[D_*D_];
__device__ __half g_w1t[D_*D_];
__device__ __half g_w2t[D_*D_];

// ---------------- helpers ------------------------------------------------------
__device__ __forceinline__ uint32_t smem_u32(const void* p) {
    uint32_t a;
    asm("{ .reg .u64 t; cvta.to.shared.u64 t, %1; cvt.u32.u64 %0, t; }" : "=r"(a) : "l"(p));
    return a;
}
__device__ __forceinline__ void cpa16u(uint32_t dst, const void* g) {
    asm volatile("cp.async.cg.shared.global [%0], [%1], 16;" :: "r"(dst), "l"(g));
}
#define CP_COMMIT() asm volatile("cp.async.commit_group;")
#define CP_WAIT1()  asm volatile("cp.async.wait_group 1;")

__device__ __forceinline__ void ldsm4(uint32_t& r0, uint32_t& r1, uint32_t& r2,
                                      uint32_t& r3, uint32_t a) {
    asm volatile("ldmatrix.sync.aligned.m8n8.x4.shared.b16 {%0,%1,%2,%3}, [%4];"
                 : "=r"(r0), "=r"(r1), "=r"(r2), "=r"(r3) : "r"(a));
}
__device__ __forceinline__ void mma_f16(float c[4], uint32_t a0, uint32_t a1,
                                        uint32_t a2, uint32_t a3,
                                        uint32_t b0, uint32_t b1) {
    asm volatile(
        "mma.sync.aligned.m16n8k16.row.col.f32.f16.f16.f32 "
        "{%0,%1,%2,%3}, {%4,%5,%6,%7}, {%8,%9}, {%0,%1,%2,%3};"
        : "+f"(c[0]), "+f"(c[1]), "+f"(c[2]), "+f"(c[3])
        : "r"(a0), "r"(a1), "r"(a2), "r"(a3), "r"(b0), "r"(b1));
}

// ---------------- weight transpose: fp32 [k][n] -> half [n][k] ------------------
__global__ void wtrans(const float* __restrict__ in, __half* __restrict__ out)
{
    __shared__ float s[32][33];
    const int bx = blockIdx.x * 32, by = blockIdx.y * 32;
    const int tx = threadIdx.x, ty = threadIdx.y;
    #pragma unroll
    for (int i = 0; i < 32; i += 8)
        s[ty + i][tx] = in[(size_t)(by + ty + i) * D_ + bx + tx];
    __syncthreads();
    #pragma unroll
    for (int i = 0; i < 32; i += 8)
        out[(size_t)(bx + ty + i) * D_ + by + tx] = __float2half_rn(s[tx][ty + i]);
}

// ---------------- V transpose: half [t][d] -> half [d][t] per batch ------------
__global__ void vtrans(const __half* __restrict__ in, __half* __restrict__ out)
{
    __shared__ __half s[32][40];
    const size_t zoff = (size_t)blockIdx.z * T_ * D_;
    in += zoff; out += zoff;
    const int bx = blockIdx.x * 32, by = blockIdx.y * 32;
    const int tx = threadIdx.x, ty = threadIdx.y;
    #pragma unroll
    for (int i = 0; i < 32; i += 8)
        s[ty + i][tx] = in[(size_t)(by + ty + i) * D_ + bx + tx];
    __syncthreads();
    #pragma unroll
    for (int i = 0; i < 32; i += 8)
        out[(size_t)(bx + ty + i) * T_ + by + tx] = s[tx][ty + i];
}

// ---------------- LayerNorm (reference's buggy LN), half output -----------------
__global__ void ln_kernel(const float* __restrict__ x, const float* __restrict__ gamma,
                          const float* __restrict__ beta, __half* __restrict__ out)
{
    const int row = blockIdx.x;
    const float* xr = x + (size_t)row * D_;
    float s = 0.f, ss = 0.f;
    for (int i = threadIdx.x; i < D_; i += 256) {
        float v = xr[i];
        s += v; ss += v * v;
    }
    #pragma unroll
    for (int o = 16; o; o >>= 1) {
        s  += __shfl_xor_sync(0xffffffffu, s, o);
        ss += __shfl_xor_sync(0xffffffffu, ss, o);
    }
    __shared__ float sh_s[8], sh_ss[8];
    const int w = threadIdx.x >> 5;
    if ((threadIdx.x & 31) == 0) { sh_s[w] = s; sh_ss[w] = ss; }
    __syncthreads();
    s = 0.f; ss = 0.f;
    #pragma unroll
    for (int i = 0; i < 8; i++) { s += sh_s[i]; ss += sh_ss[i]; }
    const float mu  = s * (1.0f / D_);
    const float var = (ss - (float)D_ * mu * mu) * (1.0f / (float)(D_ - 1));
    const float c   = mu * rsqrtf(var);
    __half* outr = out + (size_t)row * D_;
    for (int i = threadIdx.x; i < D_; i += 256)
        outr[i] = __float2half_rn((xr[i] - c) * gamma[i] + beta[i]);
}

// ---------------- causal softmax: fp32 S row -> half P row + zero pad -----------
__global__ void softmax_kernel(const float* __restrict__ S, __half* __restrict__ P)
{
    const int row = blockIdx.x;
    const int b = row >> 11;
    const int q = row & (T_ - 1);
    const float* r = S + (size_t)b * T_ * T_ + (size_t)q * T_;
    __half* ph = P + (size_t)b * T_ * T_ + (size_t)q * T_;
    const int n = q + 1;
    const int pad = ((q >> 7) + 1) << 7;

    float m = -1e30f;
    for (int i = threadIdx.x; i < n; i += 256) m = fmaxf(m, r[i]);
    #pragma unroll
    for (int o = 16; o; o >>= 1) m = fmaxf(m, __shfl_xor_sync(0xffffffffu, m, o));
    __shared__ float shm[8], shs[8];
    const int w = threadIdx.x >> 5;
    if ((threadIdx.x & 31) == 0) shm[w] = m;
    __syncthreads();
    m = shm[0];
    #pragma unroll
    for (int i = 1; i < 8; i++) m = fmaxf(m, shm[i]);

    float s = 0.f;
    for (int i = threadIdx.x; i < n; i += 256) s += __expf(r[i] - m);
    #pragma unroll
    for (int o = 16; o; o >>= 1) s += __shfl_xor_sync(0xffffffffu, s, o);
    if ((threadIdx.x & 31) == 0) shs[w] = s;
    __syncthreads();
    s = 0.f;
    #pragma unroll
    for (int i = 0; i < 8; i++) s += shs[i];
    const float inv = 1.0f / s;
    for (int i = threadIdx.x; i < n; i += 256)
        ph[i] = __float2half_rn(__expf(r[i] - m) * inv);
    for (int i = n + threadIdx.x; i < pad; i += 256) ph[i] = __half(0.f);
}

// ---------------- fp16 TN GEMM: C[m][n] = sum_k A[m][k]*B[n][k] ------------------
// EPI 0: half(acc); 1: half(relu(acc+bias)); 2: float acc/32; 3: float acc+resid;
// EPI 4: float acc+bias+resid
// MODE 0: plain; 1: scores (skip bn>bm); 2: AV (k bounded at bm+128)
template<int EPI, int MODE>
__global__ __launch_bounds__(NT, 2)
void hgemm(const __half* __restrict__ A, const __half* __restrict__ B, void* Cv,
           const float* __restrict__ bias, const float* __restrict__ resid,
           int K, int N, size_t sA, size_t sB, size_t sC)
{
    const int bm = blockIdx.y * BM;
    const int bn = blockIdx.x * BN;
    if (MODE == 1 && bn > bm) return;

    const int z = blockIdx.z;
    A += (size_t)z * sA;
    B += (size_t)z * sB;
    if (resid) resid += (size_t)z * sC;
    __half* Ch = (__half*)Cv + (size_t)z * sC;
    float*  Cf = (float*)Cv  + (size_t)z * sC;

    extern __shared__ char smc[];
    const uint32_t sb = smem_u32(smc);

    const int tid  = threadIdx.x;
    const int lane = tid & 31;
    const int warp = tid >> 5;
    const int g    = lane >> 2;
    const int tq   = lane & 3;
    const int wm   = (warp >> 2) * 64;
    const int wn   = (warp & 3) * 32;

    const __half* Abase = A + (size_t)bm * K;
    const __half* Bbase = B + (size_t)bn * K;

    float c[4][4][4];
    #pragma unroll
    for (int i = 0; i < 4; i++)
        #pragma unroll
        for (int j = 0; j < 4; j++)
            #pragma unroll
            for (int l = 0; l < 4; l++) c[i][j][l] = 0.f;

    const int nt = (MODE == 2) ? (bm / BK + 4) : (K / BK);

    // per-thread cp.async coords: 512 16B-chunks per tile, 2 per thread
    const int r0c = tid >> 2;            // row for chunk set 0 (0..63)
    const int cc0 = tid & 3;             // 16B col

    auto load_stage = [&](int buf, int t) {
        const int k0 = t * BK;
        const uint32_t base = sb + buf * STAGE_B;
        #pragma unroll
        for (int p = 0; p < 2; p++) {
            const int r = r0c + p * 64;
            const uint32_t da = base + r * 80 + cc0 * 16;
            cpa16u(da, Abase + (size_t)r * K + k0 + cc0 * 8);
            cpa16u(da + TILE_B, Bbase + (size_t)r * K + k0 + cc0 * 8);
        }
    };

    load_stage(0, 0); CP_COMMIT();
    load_stage(1, 1); CP_COMMIT();

    // ldmatrix lane addressing (byte offsets within a stage)
    const uint32_t a_l = (uint32_t)(wm + (lane & 15)) * 80 + (uint32_t)((lane >> 4) * 8) * 2;
    const uint32_t b_l = (uint32_t)(wn + (lane & 7) + ((lane >> 4) & 1) * 8) * 80
                       + (uint32_t)(((lane >> 3) & 1) * 8) * 2;

    for (int t = 0; t < nt; t++) {
        CP_WAIT1();
        __syncthreads();
        if (t + 2 < nt) load_stage((t + 2) % NSTAGE, t + 2);
        CP_COMMIT();

        const uint32_t sbase = sb + (t % NSTAGE) * STAGE_B;
        const uint32_t aaddr = sbase + a_l;
        const uint32_t baddr = sbase + TILE_B + b_l;

        #pragma unroll
        for (int s8 = 0; s8 < 2; s8++) {
            const uint32_t ko = s8 * 32;   // 16 halves = 32 bytes
            uint32_t af[4][4], bf[2][4];
            #pragma unroll
            for (int mt = 0; mt < 4; mt++)
                ldsm4(af[mt][0], af[mt][1], af[mt][2], af[mt][3],
                      aaddr + mt * (16 * 80) + ko);
            #pragma unroll
            for (int np = 0; np < 2; np++)
                ldsm4(bf[np][0], bf[np][1], bf[np][2], bf[np][3],
                      baddr + np * (16 * 80) + ko);
            #pragma unroll
            for (int mt = 0; mt < 4; mt++)
                #pragma unroll
                for (int ntl = 0; ntl < 4; ntl++)
                    mma_f16(c[mt][ntl],
                            af[mt][0], af[mt][1], af[mt][2], af[mt][3],
                            bf[ntl >> 1][(ntl & 1) * 2], bf[ntl >> 1][(ntl & 1) * 2 + 1]);
        }
    }

    // ---------------- epilogue ----------------
    #pragma unroll
    for (int mt = 0; mt < 4; mt++) {
        #pragma unroll
        for (int ntl = 0; ntl < 4; ntl++) {
            const int col = bn + wn + ntl * 8 + 2 * tq;
            float b0 = 0.f, b1 = 0.f;
            if (EPI == 1 || EPI == 4) { b0 = bias[col]; b1 = bias[col + 1]; }
            #pragma unroll
            for (int h = 0; h < 2; h++) {
                const int row = bm + wm + mt * 16 + g + h * 8;
                float v0 = c[mt][ntl][2 * h], v1 = c[mt][ntl][2 * h + 1];
                if (EPI == 0) {
                    *(__half2*)&Ch[(size_t)row * N + col] = __floats2half2_rn(v0, v1);
                } else if (EPI == 1) {
                    v0 = fmaxf(v0 + b0, 0.f);
                    v1 = fmaxf(v1 + b1, 0.f);
                    *(__half2*)&Ch[(size_t)row * N + col] = __floats2half2_rn(v0, v1);
                } else if (EPI == 2) {
                    float2 o; o.x = v0 * 0.03125f; o.y = v1 * 0.03125f;
                    *(float2*)&Cf[(size_t)row * N + col] = o;
                } else if (EPI == 3) {
                    float2 rv = *(const float2*)&resid[(size_t)row * N + col];
                    float2 o; o.x = v0 + rv.x; o.y = v1 + rv.y;
                    *(float2*)&Cf[(size_t)row * N + col] = o;
                } else {
                    float2 rv = *(const float2*)&resid[(size_t)row * N + col];
                    float2 o; o.x = v0 + b0 + rv.x; o.y = v1 + b1 + rv.y;
                    *(float2*)&Cf[(size_t)row * N + col] = o;
                }
            }
        }
    }
}

// ---------------- launch --------------------------------------------------------
extern "C" void kernel_launch(void* const* d_in, const int* in_sizes, int n_in,
                              void* d_out, int out_size)
{
    const float* x   = (const float*)d_in[0];
    const float* g1  = (const float*)d_in[1];
    const float* be1 = (const float*)d_in[2];
    const float* wq  = (const float*)d_in[3];
    const float* wk  = (const float*)d_in[4];
    const float* wv  = (const float*)d_in[5];
    const float* g2  = (const float*)d_in[6];
    const float* be2 = (const float*)d_in[7];
    const float* W1  = (const float*)d_in[8];
    const float* b1  = (const float*)d_in[9];
    const float* W2  = (const float*)d_in[10];
    const float* b2  = (const float*)d_in[11];
    float* out = (float*)d_out;

    __half *p_h, *p_q, *p_k, *p_v, *p_vt, *p_p, *p_h2, *p_m1;
    __half *p_wqt, *p_wkt, *p_wvt, *p_w1t, *p_w2t;
    float *p_s, *p_y;
    cudaGetSymbolAddress((void**)&p_h,   g_h);
    cudaGetSymbolAddress((void**)&p_q,   g_q);
    cudaGetSymbolAddress((void**)&p_k,   g_k);
    cudaGetSymbolAddress((void**)&p_v,   g_v);
    cudaGetSymbolAddress((void**)&p_vt,  g_vt);
    cudaGetSymbolAddress((void**)&p_p,   g_p);
    cudaGetSymbolAddress((void**)&p_s,   g_s);
    cudaGetSymbolAddress((void**)&p_y,   g_y);
    cudaGetSymbolAddress((void**)&p_h2,  g_h2);
    cudaGetSymbolAddress((void**)&p_m1,  g_m1);
    cudaGetSymbolAddress((void**)&p_wqt, g_wqt);
    cudaGetSymbolAddress((void**)&p_wkt, g_wkt);
    cudaGetSymbolAddress((void**)&p_wvt, g_wvt);
    cudaGetSymbolAddress((void**)&p_w1t, g_w1t);
    cudaGetSymbolAddress((void**)&p_w2t, g_w2t);

    cudaFuncSetAttribute(hgemm<0,0>, cudaFuncAttributeMaxDynamicSharedMemorySize, SMEM_B);
    cudaFuncSetAttribute(hgemm<1,0>, cudaFuncAttributeMaxDynamicSharedMemorySize, SMEM_B);
    cudaFuncSetAttribute(hgemm<4,0>, cudaFuncAttributeMaxDynamicSharedMemorySize, SMEM_B);
    cudaFuncSetAttribute(hgemm<2,1>, cudaFuncAttributeMaxDynamicSharedMemorySize, SMEM_B);
    cudaFuncSetAttribute(hgemm<3,2>, cudaFuncAttributeMaxDynamicSharedMemorySize, SMEM_B);

    const dim3 tb(32, 8);
    const dim3 wt_grid(D_/32, D_/32);
    const dim3 vt_grid(D_/32, T_/32, B_);
    const dim3 gemm_grid(D_/BN, M_/BM);        // (8, 64)
    const dim3 sc_grid(T_/BN, T_/BM, B_);      // (16, 16, 4)
    const dim3 av_grid(D_/BN, T_/BM, B_);      // (8, 16, 4)

    wtrans<<<wt_grid, tb>>>(wq, p_wqt);
    wtrans<<<wt_grid, tb>>>(wk, p_wkt);
    wtrans<<<wt_grid, tb>>>(wv, p_wvt);
    wtrans<<<wt_grid, tb>>>(W1, p_w1t);
    wtrans<<<wt_grid, tb>>>(W2, p_w2t);

    ln_kernel<<<M_, 256>>>(x, g1, be1, p_h);
    hgemm<0,0><<<gemm_grid, NT, SMEM_B>>>(p_h, p_wqt, p_q, nullptr, nullptr, D_, D_, 0, 0, 0);
    hgemm<0,0><<<gemm_grid, NT, SMEM_B>>>(p_h, p_wkt, p_k, nullptr, nullptr, D_, D_, 0, 0, 0);
    hgemm<0,0><<<gemm_grid, NT, SMEM_B>>>(p_h, p_wvt, p_v, nullptr, nullptr, D_, D_, 0, 0, 0);
    vtrans<<<vt_grid, tb>>>(p_v, p_vt);
    hgemm<2,1><<<sc_grid, NT, SMEM_B>>>(p_q, p_k, p_s, nullptr, nullptr, D_, T_,
                                        (size_t)T_*D_, (size_t)T_*D_, (size_t)T_*T_);
    softmax_kernel<<<M_, 256>>>(p_s, p_p);
    hgemm<3,2><<<av_grid, NT, SMEM_B>>>(p_p, p_vt, p_y, nullptr, x, T_, D_,
                                        (size_t)T_*T_, (size_t)D_*T_, (size_t)T_*D_);
    ln_kernel<<<M_, 256>>>(p_y, g2, be2, p_h2);
    hgemm<1,0><<<gemm_grid, NT, SMEM_B>>>(p_h2, p_w1t, p_m1, b1, nullptr, D_, D_, 0, 0, 0);
    hgemm<4,0><<<gemm_grid, NT, SMEM_B>>>(p_m1, p_w2t, out, b2, p_y, D_, D_, 0, 0, 0);
}

// round 6
// speedup vs baseline: 7.6583x; 1.0505x over previous
#include <cuda_runtime.h>
#include <cuda_fp16.h>
#include <math.h>
#include <stdint.h>

#define B_ 4
#define T_ 2048
#define D_ 1024
#define M_ (B_*T_)

#define NT 256
#define BM 128
#define BN 128
#define BK 32              // halves per k-chunk
#define LDHS 40            // halves per smem row (80 B stride)
#define TILE_B (128*LDHS*2)     // 10240 B per operand tile
#define STAGE_B (2*TILE_B)      // 20480 B
#define NSTAGE 3
#define SMEM_B (NSTAGE*STAGE_B) // 61440 B

// ---------------- scratch ------------------------------------------------------
__device__ __half g_h  [M_*D_];
__device__ __half g_qk [(size_t)M_*2048];
__device__ __half g_vt [(size_t)B_*D_*T_];
__device__ __half g_s  [(size_t)B_*T_*T_];
__device__ float  g_y  [M_*D_];
__device__ __half g_h2 [M_*D_];
__device__ __half g_m1 [M_*D_];
__device__ __half g_wqkt[2048*D_];
__device__ __half g_wvt[D_*D_];
__device__ __half g_w1t[D_*D_];
__device__ __half g_w2t[D_*D_];

// ---------------- helpers ------------------------------------------------------
__device__ __forceinline__ uint32_t smem_u32(const void* p) {
    uint32_t a;
    asm("{ .reg .u64 t; cvta.to.shared.u64 t, %1; cvt.u32.u64 %0, t; }" : "=r"(a) : "l"(p));
    return a;
}
__device__ __forceinline__ void cpa16u(uint32_t dst, const void* g) {
    asm volatile("cp.async.cg.shared.global [%0], [%1], 16;" :: "r"(dst), "l"(g));
}
#define CP_COMMIT() asm volatile("cp.async.commit_group;")
#define CP_WAIT1()  asm volatile("cp.async.wait_group 1;")

__device__ __forceinline__ void ldsm4(uint32_t& r0, uint32_t& r1, uint32_t& r2,
                                      uint32_t& r3, uint32_t a) {
    asm volatile("ldmatrix.sync.aligned.m8n8.x4.shared.b16 {%0,%1,%2,%3}, [%4];"
                 : "=r"(r0), "=r"(r1), "=r"(r2), "=r"(r3) : "r"(a));
}
__device__ __forceinline__ void mma_f16(float c[4], uint32_t a0, uint32_t a1,
                                        uint32_t a2, uint32_t a3,
                                        uint32_t b0, uint32_t b1) {
    asm volatile(
        "mma.sync.aligned.m16n8k16.row.col.f32.f16.f16.f32 "
        "{%0,%1,%2,%3}, {%4,%5,%6,%7}, {%8,%9}, {%0,%1,%2,%3};"
        : "+f"(c[0]), "+f"(c[1]), "+f"(c[2]), "+f"(c[3])
        : "r"(a0), "r"(a1), "r"(a2), "r"(a3), "r"(b0), "r"(b1));
}

// ---------------- weight transpose: fp32 [k][n] -> half [n][k] ------------------
__global__ void wtrans(const float* __restrict__ in, __half* __restrict__ out)
{
    __shared__ float s[32][33];
    const int bx = blockIdx.x * 32, by = blockIdx.y * 32;
    const int tx = threadIdx.x, ty = threadIdx.y;
    #pragma unroll
    for (int i = 0; i < 32; i += 8)
        s[ty + i][tx] = in[(size_t)(by + ty + i) * D_ + bx + tx];
    __syncthreads();
    #pragma unroll
    for (int i = 0; i < 32; i += 8)
        out[(size_t)(bx + ty + i) * D_ + by + tx] = __float2half_rn(s[tx][ty + i]);
}

// ---------------- LayerNorm (reference's buggy LN), half output -----------------
__global__ void ln_kernel(const float* __restrict__ x, const float* __restrict__ gamma,
                          const float* __restrict__ beta, __half* __restrict__ out)
{
    const int row = blockIdx.x;
    const float* xr = x + (size_t)row * D_;
    float s = 0.f, ss = 0.f;
    const float4* x4 = (const float4*)xr;
    for (int i = threadIdx.x; i < D_/4; i += 256) {
        float4 v = x4[i];
        s += v.x + v.y + v.z + v.w;
        ss += v.x*v.x + v.y*v.y + v.z*v.z + v.w*v.w;
    }
    #pragma unroll
    for (int o = 16; o; o >>= 1) {
        s  += __shfl_xor_sync(0xffffffffu, s, o);
        ss += __shfl_xor_sync(0xffffffffu, ss, o);
    }
    __shared__ float sh_s[8], sh_ss[8];
    const int w = threadIdx.x >> 5;
    if ((threadIdx.x & 31) == 0) { sh_s[w] = s; sh_ss[w] = ss; }
    __syncthreads();
    s = 0.f; ss = 0.f;
    #pragma unroll
    for (int i = 0; i < 8; i++) { s += sh_s[i]; ss += sh_ss[i]; }
    const float mu  = s * (1.0f / D_);
    const float var = (ss - (float)D_ * mu * mu) * (1.0f / (float)(D_ - 1));
    const float c   = mu * rsqrtf(var);
    __half2* o2 = (__half2*)(out + (size_t)row * D_);
    for (int i = threadIdx.x; i < D_/4; i += 256) {
        float4 v = x4[i];
        const int j = i * 4;
        o2[2*i]   = __floats2half2_rn((v.x - c) * gamma[j]   + beta[j],
                                      (v.y - c) * gamma[j+1] + beta[j+1]);
        o2[2*i+1] = __floats2half2_rn((v.z - c) * gamma[j+2] + beta[j+2],
                                      (v.w - c) * gamma[j+3] + beta[j+3]);
    }
}

// ---------------- causal softmax in place on half S -----------------------------
__global__ void softmax_kernel(__half* __restrict__ S)
{
    const int row = blockIdx.x;
    const int b = row >> 11;
    const int q = row & (T_ - 1);
    __half* r = S + (size_t)b * T_ * T_ + (size_t)q * T_;
    const int n = q + 1;
    const int pad = ((q >> 7) + 1) << 7;

    float m = -1e30f;
    for (int i = threadIdx.x; i < n; i += 256) m = fmaxf(m, __half2float(r[i]));
    #pragma unroll
    for (int o = 16; o; o >>= 1) m = fmaxf(m, __shfl_xor_sync(0xffffffffu, m, o));
    __shared__ float shm[8], shs[8];
    const int w = threadIdx.x >> 5;
    if ((threadIdx.x & 31) == 0) shm[w] = m;
    __syncthreads();
    m = shm[0];
    #pragma unroll
    for (int i = 1; i < 8; i++) m = fmaxf(m, shm[i]);

    float s = 0.f;
    for (int i = threadIdx.x; i < n; i += 256) s += __expf(__half2float(r[i]) - m);
    #pragma unroll
    for (int o = 16; o; o >>= 1) s += __shfl_xor_sync(0xffffffffu, s, o);
    if ((threadIdx.x & 31) == 0) shs[w] = s;
    __syncthreads();
    s = 0.f;
    #pragma unroll
    for (int i = 0; i < 8; i++) s += shs[i];
    const float inv = 1.0f / s;
    for (int i = threadIdx.x; i < n; i += 256)
        r[i] = __float2half_rn(__expf(__half2float(r[i]) - m) * inv);
    for (int i = n + threadIdx.x; i < pad; i += 256) r[i] = __half(0.f);
}

// ---------------- fp16 TN GEMM: C[m][n] = sum_k A[m][k]*B[n][k] ------------------
// EPI 0: half(acc); 1: half(relu(acc+bias)); 2: half(acc/32); 3: float acc+resid;
// EPI 4: float acc+bias+resid
// MODE 0: plain; 1: scores (skip bn>bm); 2: AV (k bounded at bm+128)
template<int EPI, int MODE>
__global__ __launch_bounds__(NT, 2)
void hgemm(const __half* __restrict__ A, const __half* __restrict__ B, void* Cv,
           const float* __restrict__ bias, const float* __restrict__ resid,
           int lda, int ldb, int K, int N, size_t sA, size_t sB, size_t sC)
{
    const int bm = blockIdx.y * BM;
    const int bn = blockIdx.x * BN;
    if (MODE == 1 && bn > bm) return;

    const int z = blockIdx.z;
    A += (size_t)z * sA;
    B += (size_t)z * sB;
    if (resid) resid += (size_t)z * sC;
    __half* Ch = (__half*)Cv + (size_t)z * sC;
    float*  Cf = (float*)Cv  + (size_t)z * sC;

    extern __shared__ char smc[];
    const uint32_t sb = smem_u32(smc);

    const int tid  = threadIdx.x;
    const int lane = tid & 31;
    const int warp = tid >> 5;
    const int g    = lane >> 2;
    const int tq   = lane & 3;
    const int wm   = (warp >> 2) * 64;
    const int wn   = (warp & 3) * 32;

    const __half* Abase = A + (size_t)bm * lda;
    const __half* Bbase = B + (size_t)bn * ldb;

    float c[4][4][4];
    #pragma unroll
    for (int i = 0; i < 4; i++)
        #pragma unroll
        for (int j = 0; j < 4; j++)
            #pragma unroll
            for (int l = 0; l < 4; l++) c[i][j][l] = 0.f;

    const int nt = (MODE == 2) ? (bm / BK + 4) : (K / BK);

    const int r0c = tid >> 2;
    const int cc0 = tid & 3;

    auto load_stage = [&](int buf, int t) {
        const int k0 = t * BK;
        const uint32_t base = sb + buf * STAGE_B;
        #pragma unroll
        for (int p = 0; p < 2; p++) {
            const int r = r0c + p * 64;
            const uint32_t da = base + r * 80 + cc0 * 16;
            cpa16u(da, Abase + (size_t)r * lda + k0 + cc0 * 8);
            cpa16u(da + TILE_B, Bbase + (size_t)r * ldb + k0 + cc0 * 8);
        }
    };

    load_stage(0, 0); CP_COMMIT();
    load_stage(1, 1); CP_COMMIT();

    const uint32_t a_l = (uint32_t)(wm + (lane & 15)) * 80 + (uint32_t)((lane >> 4) * 8) * 2;
    const uint32_t b_l = (uint32_t)(wn + (lane & 7) + ((lane >> 4) & 1) * 8) * 80
                       + (uint32_t)(((lane >> 3) & 1) * 8) * 2;

    for (int t = 0; t < nt; t++) {
        CP_WAIT1();
        __syncthreads();
        if (t + 2 < nt) load_stage((t + 2) % NSTAGE, t + 2);
        CP_COMMIT();

        const uint32_t sbase = sb + (t % NSTAGE) * STAGE_B;
        const uint32_t aaddr = sbase + a_l;
        const uint32_t baddr = sbase + TILE_B + b_l;

        #pragma unroll
        for (int s8 = 0; s8 < 2; s8++) {
            const uint32_t ko = s8 * 32;
            uint32_t af[4][4], bf[2][4];
            #pragma unroll
            for (int mt = 0; mt < 4; mt++)
                ldsm4(af[mt][0], af[mt][1], af[mt][2], af[mt][3],
                      aaddr + mt * (16 * 80) + ko);
            #pragma unroll
            for (int np = 0; np < 2; np++)
                ldsm4(bf[np][0], bf[np][1], bf[np][2], bf[np][3],
                      baddr + np * (16 * 80) + ko);
            #pragma unroll
            for (int mt = 0; mt < 4; mt++)
                #pragma unroll
                for (int ntl = 0; ntl < 4; ntl++)
                    mma_f16(c[mt][ntl],
                            af[mt][0], af[mt][1], af[mt][2], af[mt][3],
                            bf[ntl >> 1][(ntl & 1) * 2], bf[ntl >> 1][(ntl & 1) * 2 + 1]);
        }
    }

    // ---------------- epilogue ----------------
    #pragma unroll
    for (int mt = 0; mt < 4; mt++) {
        #pragma unroll
        for (int ntl = 0; ntl < 4; ntl++) {
            const int col = bn + wn + ntl * 8 + 2 * tq;
            float b0 = 0.f, b1 = 0.f;
            if (EPI == 1 || EPI == 4) { b0 = bias[col]; b1 = bias[col + 1]; }
            #pragma unroll
            for (int h = 0; h < 2; h++) {
                const int row = bm + wm + mt * 16 + g + h * 8;
                float v0 = c[mt][ntl][2 * h], v1 = c[mt][ntl][2 * h + 1];
                if (EPI == 0) {
                    *(__half2*)&Ch[(size_t)row * N + col] = __floats2half2_rn(v0, v1);
                } else if (EPI == 1) {
                    v0 = fmaxf(v0 + b0, 0.f);
                    v1 = fmaxf(v1 + b1, 0.f);
                    *(__half2*)&Ch[(size_t)row * N + col] = __floats2half2_rn(v0, v1);
                } else if (EPI == 2) {
                    *(__half2*)&Ch[(size_t)row * N + col] =
                        __floats2half2_rn(v0 * 0.03125f, v1 * 0.03125f);
                } else if (EPI == 3) {
                    float2 rv = *(const float2*)&resid[(size_t)row * N + col];
                    float2 o; o.x = v0 + rv.x; o.y = v1 + rv.y;
                    *(float2*)&Cf[(size_t)row * N + col] = o;
                } else {
                    float2 rv = *(const float2*)&resid[(size_t)row * N + col];
                    float2 o; o.x = v0 + b0 + rv.x; o.y = v1 + b1 + rv.y;
                    *(float2*)&Cf[(size_t)row * N + col] = o;
                }
            }
        }
    }
}

// ---------------- launch --------------------------------------------------------
extern "C" void kernel_launch(void* const* d_in, const int* in_sizes, int n_in,
                              void* d_out, int out_size)
{
    const float* x   = (const float*)d_in[0];
    const float* g1  = (const float*)d_in[1];
    const float* be1 = (const float*)d_in[2];
    const float* wq  = (const float*)d_in[3];
    const float* wk  = (const float*)d_in[4];
    const float* wv  = (const float*)d_in[5];
    const float* g2  = (const float*)d_in[6];
    const float* be2 = (const float*)d_in[7];
    const float* W1  = (const float*)d_in[8];
    const float* b1  = (const float*)d_in[9];
    const float* W2  = (const float*)d_in[10];
    const float* b2  = (const float*)d_in[11];
    float* out = (float*)d_out;

    __half *p_h, *p_qk, *p_vt, *p_s, *p_h2, *p_m1;
    __half *p_wqkt, *p_wvt, *p_w1t, *p_w2t;
    float *p_y;
    cudaGetSymbolAddress((void**)&p_h,    g_h);
    cudaGetSymbolAddress((void**)&p_qk,   g_qk);
    cudaGetSymbolAddress((void**)&p_vt,   g_vt);
    cudaGetSymbolAddress((void**)&p_s,    g_s);
    cudaGetSymbolAddress((void**)&p_y,    g_y);
    cudaGetSymbolAddress((void**)&p_h2,   g_h2);
    cudaGetSymbolAddress((void**)&p_m1,   g_m1);
    cudaGetSymbolAddress((void**)&p_wqkt, g_wqkt);
    cudaGetSymbolAddress((void**)&p_wvt,  g_wvt);
    cudaGetSymbolAddress((void**)&p_w1t,  g_w1t);
    cudaGetSymbolAddress((void**)&p_w2t,  g_w2t);

    cudaFuncSetAttribute(hgemm<0,0>, cudaFuncAttributeMaxDynamicSharedMemorySize, SMEM_B);
    cudaFuncSetAttribute(hgemm<1,0>, cudaFuncAttributeMaxDynamicSharedMemorySize, SMEM_B);
    cudaFuncSetAttribute(hgemm<4,0>, cudaFuncAttributeMaxDynamicSharedMemorySize, SMEM_B);
    cudaFuncSetAttribute(hgemm<2,1>, cudaFuncAttributeMaxDynamicSharedMemorySize, SMEM_B);
    cudaFuncSetAttribute(hgemm<3,2>, cudaFuncAttributeMaxDynamicSharedMemorySize, SMEM_B);

    const dim3 tb(32, 8);
    const dim3 wt_grid(D_/32, D_/32);
    const dim3 qk_grid(2048/BN, M_/BM);        // (16, 64) = 1024 CTAs
    const dim3 vt_grid(T_/BN, D_/BM, B_);      // (16, 8, 4)
    const dim3 mlp_grid(D_/BN, M_/BM);         // (8, 64)
    const dim3 sc_grid(T_/BN, T_/BM, B_);      // (16, 16, 4)
    const dim3 av_grid(D_/BN, T_/BM, B_);      // (8, 16, 4)

    wtrans<<<wt_grid, tb>>>(wq, p_wqkt);
    wtrans<<<wt_grid, tb>>>(wk, p_wqkt + (size_t)1024 * D_);
    wtrans<<<wt_grid, tb>>>(wv, p_wvt);
    wtrans<<<wt_grid, tb>>>(W1, p_w1t);
    wtrans<<<wt_grid, tb>>>(W2, p_w2t);

    ln_kernel<<<M_, 256>>>(x, g1, be1, p_h);
    // qk = h @ [wq|wk]   (N=2048)
    hgemm<0,0><<<qk_grid, NT, SMEM_B>>>(p_h, p_wqkt, p_qk, nullptr, nullptr,
                                        D_, D_, D_, 2048, 0, 0, 0);
    // vt[b][d][t] = sum_k wvt[d][k] * h[b*T+t][k]
    hgemm<0,0><<<vt_grid, NT, SMEM_B>>>(p_wvt, p_h, p_vt, nullptr, nullptr,
                                        D_, D_, D_, T_, 0, (size_t)T_*D_, (size_t)D_*T_);
    // scores: A=q (qk cols 0-1023), B=k (qk cols 1024-2047)
    hgemm<2,1><<<sc_grid, NT, SMEM_B>>>(p_qk, p_qk + 1024, p_s, nullptr, nullptr,
                                        2048, 2048, D_, T_,
                                        (size_t)T_*2048, (size_t)T_*2048, (size_t)T_*T_);
    softmax_kernel<<<M_, 256>>>(p_s);
    hgemm<3,2><<<av_grid, NT, SMEM_B>>>(p_s, p_vt, p_y, nullptr, x,
                                        T_, T_, T_, D_,
                                        (size_t)T_*T_, (size_t)D_*T_, (size_t)T_*D_);
    ln_kernel<<<M_, 256>>>(p_y, g2, be2, p_h2);
    hgemm<1,0><<<mlp_grid, NT, SMEM_B>>>(p_h2, p_w1t, p_m1, b1, nullptr,
                                         D_, D_, D_, D_, 0, 0, 0);
    hgemm<4,0><<<mlp_grid, NT, SMEM_B>>>(p_m1, p_w2t, out, b2, p_y,
                                         D_, D_, D_, D_, 0, 0, 0);
}

// round 7
// speedup vs baseline: 7.7315x; 1.0096x over previous
#include <cuda_runtime.h>
#include <cuda_fp16.h>
#include <math.h>
#include <stdint.h>

#define B_ 4
#define T_ 2048
#define D_ 1024
#define M_ (B_*T_)

#define NT 256
#define BM 128
#define BN 128
#define BK 32
#define TILE_B (128*40*2)       // 10240 B per operand tile (80 B row stride)
#define STAGE_B (2*TILE_B)      // 20480 B
#define NSTAGE 3
#define SMEM_B (NSTAGE*STAGE_B) // 61440 B
#define GRID_P 304              // persistent CTAs (2 per SM, 152 SMs)

// ---------------- scratch ------------------------------------------------------
__device__ __half g_h  [M_*D_];
__device__ __half g_qk [(size_t)M_*2048];
__device__ __half g_vt [(size_t)B_*D_*T_];
__device__ __half g_s  [(size_t)B_*T_*T_];
__device__ float  g_y  [M_*D_];
__device__ __half g_h2 [M_*D_];
__device__ __half g_m1 [M_*D_];
__device__ __half g_wqkt[2048*D_];
__device__ __half g_wvt[D_*D_];
__device__ __half g_w1t[D_*D_];
__device__ __half g_w2t[D_*D_];

// ---------------- helpers ------------------------------------------------------
__device__ __forceinline__ uint32_t smem_u32(const void* p) {
    uint32_t a;
    asm("{ .reg .u64 t; cvta.to.shared.u64 t, %1; cvt.u32.u64 %0, t; }" : "=r"(a) : "l"(p));
    return a;
}
__device__ __forceinline__ void cpa16u(uint32_t dst, const void* g) {
    asm volatile("cp.async.cg.shared.global [%0], [%1], 16;" :: "r"(dst), "l"(g));
}
#define CP_COMMIT() asm volatile("cp.async.commit_group;")
#define CP_WAIT1()  asm volatile("cp.async.wait_group 1;")

__device__ __forceinline__ void ldsm4(uint32_t& r0, uint32_t& r1, uint32_t& r2,
                                      uint32_t& r3, uint32_t a) {
    asm volatile("ldmatrix.sync.aligned.m8n8.x4.shared.b16 {%0,%1,%2,%3}, [%4];"
                 : "=r"(r0), "=r"(r1), "=r"(r2), "=r"(r3) : "r"(a));
}
__device__ __forceinline__ void mma_f16(float c[4], uint32_t a0, uint32_t a1,
                                        uint32_t a2, uint32_t a3,
                                        uint32_t b0, uint32_t b1) {
    asm volatile(
        "mma.sync.aligned.m16n8k16.row.col.f32.f16.f16.f32 "
        "{%0,%1,%2,%3}, {%4,%5,%6,%7}, {%8,%9}, {%0,%1,%2,%3};"
        : "+f"(c[0]), "+f"(c[1]), "+f"(c[2]), "+f"(c[3])
        : "r"(a0), "r"(a1), "r"(a2), "r"(a3), "r"(b0), "r"(b1));
}

// ---------------- fused weight transpose: 5 matrices, wq scaled by 1/32 ---------
struct WT5 { const float* src[5]; __half* dst[5]; };
__global__ void wtrans5(WT5 wt)
{
    __shared__ float s[32][33];
    const float* in = wt.src[blockIdx.z];
    __half* out = wt.dst[blockIdx.z];
    const float scale = (blockIdx.z == 0) ? 0.03125f : 1.0f;
    const int bx = blockIdx.x * 32, by = blockIdx.y * 32;
    const int tx = threadIdx.x, ty = threadIdx.y;
    #pragma unroll
    for (int i = 0; i < 32; i += 8)
        s[ty + i][tx] = in[(size_t)(by + ty + i) * D_ + bx + tx] * scale;
    __syncthreads();
    #pragma unroll
    for (int i = 0; i < 32; i += 8)
        out[(size_t)(bx + ty + i) * D_ + by + tx] = __float2half_rn(s[tx][ty + i]);
}

// ---------------- LayerNorm (reference's buggy LN), half output -----------------
__global__ void ln_kernel(const float* __restrict__ x, const float* __restrict__ gamma,
                          const float* __restrict__ beta, __half* __restrict__ out)
{
    const int row = blockIdx.x;
    const float* xr = x + (size_t)row * D_;
    float s = 0.f, ss = 0.f;
    const float4* x4 = (const float4*)xr;
    for (int i = threadIdx.x; i < D_/4; i += 256) {
        float4 v = x4[i];
        s += v.x + v.y + v.z + v.w;
        ss += v.x*v.x + v.y*v.y + v.z*v.z + v.w*v.w;
    }
    #pragma unroll
    for (int o = 16; o; o >>= 1) {
        s  += __shfl_xor_sync(0xffffffffu, s, o);
        ss += __shfl_xor_sync(0xffffffffu, ss, o);
    }
    __shared__ float sh_s[8], sh_ss[8];
    const int w = threadIdx.x >> 5;
    if ((threadIdx.x & 31) == 0) { sh_s[w] = s; sh_ss[w] = ss; }
    __syncthreads();
    s = 0.f; ss = 0.f;
    #pragma unroll
    for (int i = 0; i < 8; i++) { s += sh_s[i]; ss += sh_ss[i]; }
    const float mu  = s * (1.0f / D_);
    const float var = (ss - (float)D_ * mu * mu) * (1.0f / (float)(D_ - 1));
    const float c   = mu * rsqrtf(var);
    __half2* o2 = (__half2*)(out + (size_t)row * D_);
    for (int i = threadIdx.x; i < D_/4; i += 256) {
        float4 v = x4[i];
        const int j = i * 4;
        o2[2*i]   = __floats2half2_rn((v.x - c) * gamma[j]   + beta[j],
                                      (v.y - c) * gamma[j+1] + beta[j+1]);
        o2[2*i+1] = __floats2half2_rn((v.z - c) * gamma[j+2] + beta[j+2],
                                      (v.w - c) * gamma[j+3] + beta[j+3]);
    }
}

// ---------------- register-cached causal softmax (1 read + 1 write) -------------
__global__ void softmax_kernel(__half* __restrict__ S)
{
    const int row = blockIdx.x;
    const int b = row >> 11;
    const int q = row & (T_ - 1);
    __half2* r2 = (__half2*)(S + (size_t)b * T_ * T_ + (size_t)q * T_);
    const int n = q + 1;                   // valid elements
    const int nh2 = (n + 1) >> 1;          // half2 words touching valid region
    const int pad2 = (((q >> 7) + 1) << 7) >> 1;  // half2 words to tile boundary
    const int tid = threadIdx.x;

    float2 ex[4];
    float m = -1e30f;
    #pragma unroll
    for (int j = 0; j < 4; j++) {
        const int i = tid + j * 256;
        float2 v = make_float2(-1e30f, -1e30f);
        if (i < nh2) {
            __half2 h = r2[i];
            v.x = __half2float(__low2half(h));
            v.y = (2 * i + 1 < n) ? __half2float(__high2half(h)) : -1e30f;
        }
        ex[j] = v;
        m = fmaxf(m, fmaxf(v.x, v.y));
    }
    #pragma unroll
    for (int o = 16; o; o >>= 1) m = fmaxf(m, __shfl_xor_sync(0xffffffffu, m, o));
    __shared__ float shm[8], shs[8];
    const int w = tid >> 5;
    if ((tid & 31) == 0) shm[w] = m;
    __syncthreads();
    m = shm[0];
    #pragma unroll
    for (int i = 1; i < 8; i++) m = fmaxf(m, shm[i]);

    float s = 0.f;
    #pragma unroll
    for (int j = 0; j < 4; j++) {
        float e0 = (ex[j].x > -1e29f) ? __expf(ex[j].x - m) : 0.f;
        float e1 = (ex[j].y > -1e29f) ? __expf(ex[j].y - m) : 0.f;
        ex[j].x = e0; ex[j].y = e1;
        s += e0 + e1;
    }
    #pragma unroll
    for (int o = 16; o; o >>= 1) s += __shfl_xor_sync(0xffffffffu, s, o);
    if ((tid & 31) == 0) shs[w] = s;
    __syncthreads();
    s = 0.f;
    #pragma unroll
    for (int i = 0; i < 8; i++) s += shs[i];
    const float inv = 1.0f / s;

    #pragma unroll
    for (int j = 0; j < 4; j++) {
        const int i = tid + j * 256;
        if (i < pad2) {
            float2 o = (i < nh2) ? make_float2(ex[j].x * inv, ex[j].y * inv)
                                 : make_float2(0.f, 0.f);
            r2[i] = __floats2half2_rn(o.x, o.y);
        }
    }
}

// ---------------- persistent fp16 TN GEMM -------------------------------------
// EPI 0: half(acc); 1: half(relu(acc+bias)); 3: float acc+resid; 4: float acc+bias+resid
// MODE 0: plain flattened (z,y,x); 1: scores lower-triangle; 2: AV (k bound at bm+128)
template<int EPI, int MODE>
__global__ __launch_bounds__(NT, 2)
void hgemm(const __half* __restrict__ A0, const __half* __restrict__ B0, void* Cv,
           const float* __restrict__ bias, const float* __restrict__ resid0,
           int lda, int ldb, int K, int N,
           size_t sA, size_t sB, size_t sC,
           int ntx, int nty, int ntz)
{
    extern __shared__ char smc[];
    const uint32_t sb = smem_u32(smc);

    const int tid  = threadIdx.x;
    const int lane = tid & 31;
    const int warp = tid >> 5;
    const int g    = lane >> 2;
    const int tq   = lane & 3;
    const int wm   = (warp >> 2) * 64;
    const int wn   = (warp & 3) * 32;
    const int r0c  = tid >> 2;
    const int cc0  = tid & 3;

    const uint32_t a_l = (uint32_t)(wm + (lane & 15)) * 80 + (uint32_t)((lane >> 4) * 8) * 2;
    const uint32_t b_l = (uint32_t)(wn + (lane & 7) + ((lane >> 4) & 1) * 8) * 80
                       + (uint32_t)(((lane >> 3) & 1) * 8) * 2;

    const int tri = nty * (nty + 1) / 2;
    const int ntiles = (MODE == 1) ? ntz * tri : ntx * nty * ntz;

    for (int tile = blockIdx.x; tile < ntiles; tile += GRID_P) {
        int tx, ty, tz;
        if (MODE == 1) {
            tz = tile / tri;
            int t = tile - tz * tri;
            ty = 0;
            while (t >= ty + 1) { t -= ty + 1; ty++; }   // row ty has ty+1 tiles
            tx = t;
        } else {
            tx = tile % ntx;
            ty = (tile / ntx) % nty;
            tz = tile / (ntx * nty);
        }
        const int bm = ty * BM;
        const int bn = tx * BN;

        const __half* A = A0 + (size_t)tz * sA + (size_t)bm * lda;
        const __half* Bm = B0 + (size_t)tz * sB + (size_t)bn * ldb;
        __half* Ch = (__half*)Cv + (size_t)tz * sC;
        float*  Cf = (float*)Cv  + (size_t)tz * sC;
        const float* resid = resid0 ? resid0 + (size_t)tz * sC : resid0;

        float c[4][4][4];
        #pragma unroll
        for (int i = 0; i < 4; i++)
            #pragma unroll
            for (int j = 0; j < 4; j++)
                #pragma unroll
                for (int l = 0; l < 4; l++) c[i][j][l] = 0.f;

        const int nt = (MODE == 2) ? (bm / BK + 4) : (K / BK);

        __syncthreads();   // protect smem stages from previous tile's readers

        auto load_stage = [&](int buf, int t) {
            const int k0 = t * BK;
            const uint32_t base = sb + buf * STAGE_B;
            #pragma unroll
            for (int p = 0; p < 2; p++) {
                const int r = r0c + p * 64;
                const uint32_t da = base + r * 80 + cc0 * 16;
                cpa16u(da, A + (size_t)r * lda + k0 + cc0 * 8);
                cpa16u(da + TILE_B, Bm + (size_t)r * ldb + k0 + cc0 * 8);
            }
        };

        load_stage(0, 0); CP_COMMIT();
        load_stage(1, 1); CP_COMMIT();

        for (int t = 0; t < nt; t++) {
            CP_WAIT1();
            __syncthreads();
            if (t + 2 < nt) load_stage((t + 2) % NSTAGE, t + 2);
            CP_COMMIT();

            const uint32_t sbase = sb + (t % NSTAGE) * STAGE_B;
            const uint32_t aaddr = sbase + a_l;
            const uint32_t baddr = sbase + TILE_B + b_l;

            #pragma unroll
            for (int s8 = 0; s8 < 2; s8++) {
                const uint32_t ko = s8 * 32;
                uint32_t af[4][4], bf[2][4];
                #pragma unroll
                for (int mt = 0; mt < 4; mt++)
                    ldsm4(af[mt][0], af[mt][1], af[mt][2], af[mt][3],
                          aaddr + mt * (16 * 80) + ko);
                #pragma unroll
                for (int np = 0; np < 2; np++)
                    ldsm4(bf[np][0], bf[np][1], bf[np][2], bf[np][3],
                          baddr + np * (16 * 80) + ko);
                #pragma unroll
                for (int mt = 0; mt < 4; mt++)
                    #pragma unroll
                    for (int ntl = 0; ntl < 4; ntl++)
                        mma_f16(c[mt][ntl],
                                af[mt][0], af[mt][1], af[mt][2], af[mt][3],
                                bf[ntl >> 1][(ntl & 1) * 2], bf[ntl >> 1][(ntl & 1) * 2 + 1]);
            }
        }

        // ---------------- epilogue ----------------
        #pragma unroll
        for (int mt = 0; mt < 4; mt++) {
            #pragma unroll
            for (int ntl = 0; ntl < 4; ntl++) {
                const int col = bn + wn + ntl * 8 + 2 * tq;
                float b0 = 0.f, b1 = 0.f;
                if (EPI == 1 || EPI == 4) { b0 = bias[col]; b1 = bias[col + 1]; }
                #pragma unroll
                for (int h = 0; h < 2; h++) {
                    const int row = bm + wm + mt * 16 + g + h * 8;
                    float v0 = c[mt][ntl][2 * h], v1 = c[mt][ntl][2 * h + 1];
                    if (EPI == 0) {
                        *(__half2*)&Ch[(size_t)row * N + col] = __floats2half2_rn(v0, v1);
                    } else if (EPI == 1) {
                        v0 = fmaxf(v0 + b0, 0.f);
                        v1 = fmaxf(v1 + b1, 0.f);
                        *(__half2*)&Ch[(size_t)row * N + col] = __floats2half2_rn(v0, v1);
                    } else if (EPI == 3) {
                        float2 rv = *(const float2*)&resid[(size_t)row * N + col];
                        float2 o; o.x = v0 + rv.x; o.y = v1 + rv.y;
                        *(float2*)&Cf[(size_t)row * N + col] = o;
                    } else {
                        float2 rv = *(const float2*)&resid[(size_t)row * N + col];
                        float2 o; o.x = v0 + b0 + rv.x; o.y = v1 + b1 + rv.y;
                        *(float2*)&Cf[(size_t)row * N + col] = o;
                    }
                }
            }
        }
    }
}

// ---------------- launch --------------------------------------------------------
extern "C" void kernel_launch(void* const* d_in, const int* in_sizes, int n_in,
                              void* d_out, int out_size)
{
    const float* x   = (const float*)d_in[0];
    const float* g1  = (const float*)d_in[1];
    const float* be1 = (const float*)d_in[2];
    const float* wq  = (const float*)d_in[3];
    const float* wk  = (const float*)d_in[4];
    const float* wv  = (const float*)d_in[5];
    const float* g2  = (const float*)d_in[6];
    const float* be2 = (const float*)d_in[7];
    const float* W1  = (const float*)d_in[8];
    const float* b1  = (const float*)d_in[9];
    const float* W2  = (const float*)d_in[10];
    const float* b2  = (const float*)d_in[11];
    float* out = (float*)d_out;

    __half *p_h, *p_qk, *p_vt, *p_s, *p_h2, *p_m1;
    __half *p_wqkt, *p_wvt, *p_w1t, *p_w2t;
    float *p_y;
    cudaGetSymbolAddress((void**)&p_h,    g_h);
    cudaGetSymbolAddress((void**)&p_qk,   g_qk);
    cudaGetSymbolAddress((void**)&p_vt,   g_vt);
    cudaGetSymbolAddress((void**)&p_s,    g_s);
    cudaGetSymbolAddress((void**)&p_y,    g_y);
    cudaGetSymbolAddress((void**)&p_h2,   g_h2);
    cudaGetSymbolAddress((void**)&p_m1,   g_m1);
    cudaGetSymbolAddress((void**)&p_wqkt, g_wqkt);
    cudaGetSymbolAddress((void**)&p_wvt,  g_wvt);
    cudaGetSymbolAddress((void**)&p_w1t,  g_w1t);
    cudaGetSymbolAddress((void**)&p_w2t,  g_w2t);

    cudaFuncSetAttribute(hgemm<0,0>, cudaFuncAttributeMaxDynamicSharedMemorySize, SMEM_B);
    cudaFuncSetAttribute(hgemm<1,0>, cudaFuncAttributeMaxDynamicSharedMemorySize, SMEM_B);
    cudaFuncSetAttribute(hgemm<4,0>, cudaFuncAttributeMaxDynamicSharedMemorySize, SMEM_B);
    cudaFuncSetAttribute(hgemm<0,1>, cudaFuncAttributeMaxDynamicSharedMemorySize, SMEM_B);
    cudaFuncSetAttribute(hgemm<3,2>, cudaFuncAttributeMaxDynamicSharedMemorySize, SMEM_B);

    WT5 wt;
    wt.src[0] = wq; wt.dst[0] = p_wqkt;
    wt.src[1] = wk; wt.dst[1] = p_wqkt + (size_t)1024 * D_;
    wt.src[2] = wv; wt.dst[2] = p_wvt;
    wt.src[3] = W1; wt.dst[3] = p_w1t;
    wt.src[4] = W2; wt.dst[4] = p_w2t;
    wtrans5<<<dim3(D_/32, D_/32, 5), dim3(32, 8)>>>(wt);

    ln_kernel<<<M_, 256>>>(x, g1, be1, p_h);
    // qk = h @ [wq/32 | wk]   (N=2048)
    hgemm<0,0><<<GRID_P, NT, SMEM_B>>>(p_h, p_wqkt, p_qk, nullptr, nullptr,
                                       D_, D_, D_, 2048, 0, 0, 0, 16, 64, 1);
    // vt[b][d][t] = sum_k wvt[d][k] * h[b*T+t][k]
    hgemm<0,0><<<GRID_P, NT, SMEM_B>>>(p_wvt, p_h, p_vt, nullptr, nullptr,
                                       D_, D_, D_, T_, 0, (size_t)T_*D_, (size_t)D_*T_,
                                       16, 8, 4);
    // scores (pre-scaled q): lower triangle only
    hgemm<0,1><<<GRID_P, NT, SMEM_B>>>(p_qk, p_qk + 1024, p_s, nullptr, nullptr,
                                       2048, 2048, D_, T_,
                                       (size_t)T_*2048, (size_t)T_*2048, (size_t)T_*T_,
                                       16, 16, 4);
    softmax_kernel<<<M_, 256>>>(p_s);
    hgemm<3,2><<<GRID_P, NT, SMEM_B>>>(p_s, p_vt, p_y, nullptr, x,
                                       T_, T_, T_, D_,
                                       (size_t)T_*T_, (size_t)D_*T_, (size_t)T_*D_,
                                       8, 16, 4);
    ln_kernel<<<M_, 256>>>(p_y, g2, be2, p_h2);
    hgemm<1,0><<<GRID_P, NT, SMEM_B>>>(p_h2, p_w1t, p_m1, b1, nullptr,
                                       D_, D_, D_, D_, 0, 0, 0, 8, 64, 1);
    hgemm<4,0><<<GRID_P, NT, SMEM_B>>>(p_m1, p_w2t, out, b2, p_y,
                                       D_, D_, D_, D_, 0, 0, 0, 8, 64, 1);
}